// round 2
// baseline (speedup 1.0000x reference)
#include <cuda_runtime.h>
#include <cuda_bf16.h>
#include <math.h>

// Problem constants
#define B_SZ    4
#define T_SZ    2048
#define D_MODEL 1024
#define NHEAD   16
#define DHEAD   64
#define D3      (3 * D_MODEL)
#define MROWS   (B_SZ * T_SZ)          // 8192

// Scratch (static device globals — allocation-free per harness rules)
__device__ float g_qkv[(size_t)MROWS * D3];      // [8192, 3072]  ~100MB
__device__ float g_att[(size_t)MROWS * D_MODEL]; // [8192, 1024]  ~33MB

// ---------------------------------------------------------------------------
// SGEMM: C[M,N] = A[M,K] @ W[N,K]^T + bias[N]
// 128x128 block tile, BK=8, 256 threads, 8x8 register microtile per thread.
// ---------------------------------------------------------------------------
#define BM 128
#define BN 128
#define BKK 8

__global__ __launch_bounds__(256) void sgemm_bias_tn(
    const float* __restrict__ A, const float* __restrict__ W,
    const float* __restrict__ bias, float* __restrict__ C,
    int M, int N, int K)
{
    __shared__ float As[BKK][BM];
    __shared__ float Ws[BKK][BN];

    const int tid = threadIdx.x;
    const int tx = tid & 15;        // 0..15 -> 8 cols each
    const int ty = tid >> 4;        // 0..15 -> 8 rows each
    const int bm = blockIdx.y * BM;
    const int bn = blockIdx.x * BN;

    const int lrow = tid >> 1;          // 0..127
    const int lseg = (tid & 1) * 4;     // 0 or 4

    const float* Aptr = A + (size_t)(bm + lrow) * K + lseg;
    const float* Wptr = W + (size_t)(bn + lrow) * K + lseg;

    float acc[8][8];
#pragma unroll
    for (int i = 0; i < 8; i++)
#pragma unroll
        for (int j = 0; j < 8; j++) acc[i][j] = 0.f;

    for (int k0 = 0; k0 < K; k0 += BKK) {
        // prefetch from global (overlaps previous tile's tail)
        float4 av = *(const float4*)(Aptr + k0);
        float4 wv = *(const float4*)(Wptr + k0);
        __syncthreads();
        As[lseg + 0][lrow] = av.x;
        As[lseg + 1][lrow] = av.y;
        As[lseg + 2][lrow] = av.z;
        As[lseg + 3][lrow] = av.w;
        Ws[lseg + 0][lrow] = wv.x;
        Ws[lseg + 1][lrow] = wv.y;
        Ws[lseg + 2][lrow] = wv.z;
        Ws[lseg + 3][lrow] = wv.w;
        __syncthreads();

#pragma unroll
        for (int kk = 0; kk < BKK; kk++) {
            float a[8], b[8];
#pragma unroll
            for (int i = 0; i < 8; i++) a[i] = As[kk][ty * 8 + i];
#pragma unroll
            for (int j = 0; j < 8; j++) b[j] = Ws[kk][tx * 8 + j];
#pragma unroll
            for (int i = 0; i < 8; i++)
#pragma unroll
                for (int j = 0; j < 8; j++)
                    acc[i][j] = fmaf(a[i], b[j], acc[i][j]);
        }
    }

    // epilogue: add bias, vectorized stores
    const int ncol = bn + tx * 8;
    float4 b0 = *(const float4*)(bias + ncol);
    float4 b1 = *(const float4*)(bias + ncol + 4);
#pragma unroll
    for (int i = 0; i < 8; i++) {
        const int m = bm + ty * 8 + i;
        float* crow = C + (size_t)m * N + ncol;
        float4 v0, v1;
        v0.x = acc[i][0] + b0.x; v0.y = acc[i][1] + b0.y;
        v0.z = acc[i][2] + b0.z; v0.w = acc[i][3] + b0.w;
        v1.x = acc[i][4] + b1.x; v1.y = acc[i][5] + b1.y;
        v1.z = acc[i][6] + b1.z; v1.w = acc[i][7] + b1.w;
        *(float4*)(crow)     = v0;
        *(float4*)(crow + 4) = v1;
    }
}

// ---------------------------------------------------------------------------
// Flash attention (fp32, online softmax). One block = 64 queries for one (b,h).
// 256 threads: thread -> (r = tid/4 in [0,64), j = tid%4).
// S phase: thread owns cols c = j + 4*cc (interleaved, bank-friendly).
// PV phase: thread owns output dims d = j*16 + dd (blocked, vectorizable).
// ---------------------------------------------------------------------------
#define AT_S 68   // padded row stride (floats) -> conflict-free row-indexed reads

__global__ __launch_bounds__(256) void attn_kernel(
    const float* __restrict__ qkv, float* __restrict__ out)
{
    extern __shared__ float smem[];
    float* Qs = smem;                    // 64*68
    float* Ks = Qs + 64 * AT_S;
    float* Vs = Ks + 64 * AT_S;
    float* Ps = Vs + 64 * AT_S;

    const int bh = blockIdx.y;
    const int b  = bh >> 4;              // /16
    const int h  = bh & 15;
    const int q0 = blockIdx.x * 64;

    const int tid = threadIdx.x;
    const int r = tid >> 2;              // 0..63
    const int j = tid & 3;               // 0..3

    const float* base = qkv + (size_t)b * T_SZ * D3;
    const int hoff = h * DHEAD;

    // Load Q tile (64 rows x 64 cols) as float4
#pragma unroll
    for (int i = 0; i < 4; i++) {
        int fidx = tid + i * 256;        // 0..1023
        int row = fidx >> 4;
        int d4  = fidx & 15;
        float4 v = *(const float4*)(base + (size_t)(q0 + row) * D3 + hoff + d4 * 4);
        *(float4*)(&Qs[row * AT_S + d4 * 4]) = v;
    }

    float m_i = -INFINITY;
    float l_i = 0.f;
    float o[16];
#pragma unroll
    for (int i = 0; i < 16; i++) o[i] = 0.f;

    for (int kt = 0; kt < T_SZ / 64; kt++) {
        const int k0 = kt * 64;
        __syncthreads();  // previous PV done (and Q load visible on first iter path)
        // Load K and V tiles
#pragma unroll
        for (int i = 0; i < 4; i++) {
            int fidx = tid + i * 256;
            int row = fidx >> 4;
            int d4  = fidx & 15;
            const float* rp = base + (size_t)(k0 + row) * D3 + hoff + d4 * 4;
            *(float4*)(&Ks[row * AT_S + d4 * 4]) = *(const float4*)(rp + D_MODEL);
            *(float4*)(&Vs[row * AT_S + d4 * 4]) = *(const float4*)(rp + 2 * D_MODEL);
        }
        __syncthreads();

        // S = Q K^T (thread: row r, cols c = j + 4*cc)
        float s[16];
#pragma unroll
        for (int cc = 0; cc < 16; cc++) s[cc] = 0.f;
#pragma unroll
        for (int d4 = 0; d4 < 16; d4++) {
            float4 q4 = *(const float4*)(&Qs[r * AT_S + d4 * 4]);
#pragma unroll
            for (int cc = 0; cc < 16; cc++) {
                const int c = j + cc * 4;
                float4 k4 = *(const float4*)(&Ks[c * AT_S + d4 * 4]);
                s[cc] = fmaf(q4.x, k4.x, s[cc]);
                s[cc] = fmaf(q4.y, k4.y, s[cc]);
                s[cc] = fmaf(q4.z, k4.z, s[cc]);
                s[cc] = fmaf(q4.w, k4.w, s[cc]);
            }
        }

        // online softmax update
        const float scale = 0.125f;   // 1/sqrt(64)
        float mloc = -INFINITY;
#pragma unroll
        for (int cc = 0; cc < 16; cc++) {
            s[cc] *= scale;
            mloc = fmaxf(mloc, s[cc]);
        }
        mloc = fmaxf(mloc, __shfl_xor_sync(0xffffffffu, mloc, 1));
        mloc = fmaxf(mloc, __shfl_xor_sync(0xffffffffu, mloc, 2));
        const float m_new = fmaxf(m_i, mloc);
        const float corr = __expf(m_i - m_new);

        float psum = 0.f;
#pragma unroll
        for (int cc = 0; cc < 16; cc++) {
            float p = __expf(s[cc] - m_new);
            Ps[r * AT_S + j + cc * 4] = p;
            psum += p;
        }
        psum += __shfl_xor_sync(0xffffffffu, psum, 1);
        psum += __shfl_xor_sync(0xffffffffu, psum, 2);
        l_i = l_i * corr + psum;
        m_i = m_new;

#pragma unroll
        for (int i = 0; i < 16; i++) o[i] *= corr;

        __syncthreads();  // Ps fully written

        // O += P @ V (thread: row r, dims d = j*16 + dd)
#pragma unroll 8
        for (int c = 0; c < 64; c++) {
            float p = Ps[r * AT_S + c];
#pragma unroll
            for (int q = 0; q < 4; q++) {
                float4 v4 = *(const float4*)(&Vs[c * AT_S + j * 16 + q * 4]);
                o[q * 4 + 0] = fmaf(p, v4.x, o[q * 4 + 0]);
                o[q * 4 + 1] = fmaf(p, v4.y, o[q * 4 + 1]);
                o[q * 4 + 2] = fmaf(p, v4.z, o[q * 4 + 2]);
                o[q * 4 + 3] = fmaf(p, v4.w, o[q * 4 + 3]);
            }
        }
    }

    // epilogue
    const float inv = 1.f / l_i;
    float* op = out + (size_t)(b * T_SZ + q0 + r) * D_MODEL + hoff + j * 16;
#pragma unroll
    for (int q = 0; q < 4; q++) {
        float4 v;
        v.x = o[q * 4 + 0] * inv;
        v.y = o[q * 4 + 1] * inv;
        v.z = o[q * 4 + 2] * inv;
        v.w = o[q * 4 + 3] * inv;
        *(float4*)(op + q * 4) = v;
    }
}

// ---------------------------------------------------------------------------
// Launch
// ---------------------------------------------------------------------------
extern "C" void kernel_launch(void* const* d_in, const int* in_sizes, int n_in,
                              void* d_out, int out_size)
{
    const float* x     = (const float*)d_in[0];
    const float* qkv_w = (const float*)d_in[1];
    const float* qkv_b = (const float*)d_in[2];
    const float* out_w = (const float*)d_in[3];
    const float* out_b = (const float*)d_in[4];
    float* out = (float*)d_out;

    float *qkvbuf, *attbuf;
    cudaGetSymbolAddress((void**)&qkvbuf, g_qkv);
    cudaGetSymbolAddress((void**)&attbuf, g_att);

    const int attn_smem = 4 * 64 * AT_S * (int)sizeof(float);  // 69632 bytes
    cudaFuncSetAttribute(attn_kernel, cudaFuncAttributeMaxDynamicSharedMemorySize,
                         attn_smem);

    // 1) QKV projection: [8192,1024] @ [3072,1024]^T + b -> [8192,3072]
    sgemm_bias_tn<<<dim3(D3 / BN, MROWS / BM), 256>>>(
        x, qkv_w, qkv_b, qkvbuf, MROWS, D3, D_MODEL);

    // 2) Attention: 64 (b,h) pairs x 32 query tiles
    attn_kernel<<<dim3(T_SZ / 64, B_SZ * NHEAD), 256, attn_smem>>>(qkvbuf, attbuf);

    // 3) Output projection: [8192,1024] @ [1024,1024]^T + b -> [8192,1024]
    sgemm_bias_tn<<<dim3(D_MODEL / BN, MROWS / BM), 256>>>(
        attbuf, out_w, out_b, out, MROWS, D_MODEL, D_MODEL);
}

// round 5
// speedup vs baseline: 5.5219x; 5.5219x over previous
#include <cuda_runtime.h>
#include <cuda_bf16.h>
#include <math.h>

// Problem constants
#define B_SZ    4
#define T_SZ    2048
#define D_MODEL 1024
#define NHEAD   16
#define DHEAD   64
#define D3      (3 * D_MODEL)
#define MROWS   (B_SZ * T_SZ)          // 8192

// Scratch (static device globals — allocation-free per harness rules)
__device__ float g_qkv[(size_t)MROWS * D3];      // [8192, 3072]
__device__ float g_att[(size_t)MROWS * D_MODEL]; // [8192, 1024]

// ---------------------------------------------------------------------------
// Helpers
// ---------------------------------------------------------------------------
__device__ __forceinline__ unsigned f2tf(float x) {
    unsigned r;
    asm("cvt.rna.tf32.f32 %0, %1;" : "=r"(r) : "f"(x));
    return r;
}

__device__ __forceinline__ void mma_tf32(
    float& d0, float& d1, float& d2, float& d3,
    unsigned a0, unsigned a1, unsigned a2, unsigned a3,
    unsigned b0, unsigned b1)
{
    asm("mma.sync.aligned.m16n8k8.row.col.f32.tf32.tf32.f32 "
        "{%0,%1,%2,%3}, {%4,%5,%6,%7}, {%8,%9}, {%0,%1,%2,%3};"
        : "+f"(d0), "+f"(d1), "+f"(d2), "+f"(d3)
        : "r"(a0), "r"(a1), "r"(a2), "r"(a3), "r"(b0), "r"(b1));
}

// ---------------------------------------------------------------------------
// TF32 GEMM: C[M,N] = A[M,K] @ W[N,K]^T + bias[N]
// 128x128x16 tile, 256 threads (8 warps, 2x4), warp tile 64x32 (4x4 mmas).
// Smem stride 20 -> conflict-free fragment loads.
// ---------------------------------------------------------------------------
#define BM 128
#define BN 128
#define BK 16
#define SSTR 20

__global__ __launch_bounds__(256) void gemm_tf32(
    const float* __restrict__ A, const float* __restrict__ W,
    const float* __restrict__ bias, float* __restrict__ C,
    int M, int N, int K)
{
    __shared__ float As[BM][SSTR];
    __shared__ float Ws[BN][SSTR];

    const int tid  = threadIdx.x;
    const int lane = tid & 31;
    const int wid  = tid >> 5;
    const int wm = (wid >> 2) * 64;    // 0 or 64
    const int wn = (wid & 3) * 32;     // 0,32,64,96
    const int bm = blockIdx.y * BM;
    const int bn = blockIdx.x * BN;

    const int lrow = tid >> 1;         // 0..127
    const int lcol = (tid & 1) * 8;    // 0 or 8

    const float* Ap = A + (size_t)(bm + lrow) * K + lcol;
    const float* Wp = W + (size_t)(bn + lrow) * K + lcol;

    float acc[4][4][4];
#pragma unroll
    for (int i = 0; i < 4; i++)
#pragma unroll
        for (int j = 0; j < 4; j++)
#pragma unroll
            for (int r = 0; r < 4; r++) acc[i][j][r] = 0.f;

    const int qr = lane >> 2;   // 0..7
    const int qc = lane & 3;    // 0..3

    for (int k0 = 0; k0 < K; k0 += BK) {
        float4 av0 = *(const float4*)(Ap + k0);
        float4 av1 = *(const float4*)(Ap + k0 + 4);
        float4 wv0 = *(const float4*)(Wp + k0);
        float4 wv1 = *(const float4*)(Wp + k0 + 4);
        __syncthreads();
        As[lrow][lcol + 0] = __uint_as_float(f2tf(av0.x));
        As[lrow][lcol + 1] = __uint_as_float(f2tf(av0.y));
        As[lrow][lcol + 2] = __uint_as_float(f2tf(av0.z));
        As[lrow][lcol + 3] = __uint_as_float(f2tf(av0.w));
        As[lrow][lcol + 4] = __uint_as_float(f2tf(av1.x));
        As[lrow][lcol + 5] = __uint_as_float(f2tf(av1.y));
        As[lrow][lcol + 6] = __uint_as_float(f2tf(av1.z));
        As[lrow][lcol + 7] = __uint_as_float(f2tf(av1.w));
        Ws[lrow][lcol + 0] = __uint_as_float(f2tf(wv0.x));
        Ws[lrow][lcol + 1] = __uint_as_float(f2tf(wv0.y));
        Ws[lrow][lcol + 2] = __uint_as_float(f2tf(wv0.z));
        Ws[lrow][lcol + 3] = __uint_as_float(f2tf(wv0.w));
        Ws[lrow][lcol + 4] = __uint_as_float(f2tf(wv1.x));
        Ws[lrow][lcol + 5] = __uint_as_float(f2tf(wv1.y));
        Ws[lrow][lcol + 6] = __uint_as_float(f2tf(wv1.z));
        Ws[lrow][lcol + 7] = __uint_as_float(f2tf(wv1.w));
        __syncthreads();

#pragma unroll
        for (int ks = 0; ks < 2; ks++) {
            const int kc = ks * 8 + qc;
            unsigned af[4][4];
#pragma unroll
            for (int mt = 0; mt < 4; mt++) {
                const int r = wm + mt * 16 + qr;
                af[mt][0] = __float_as_uint(As[r][kc]);
                af[mt][1] = __float_as_uint(As[r + 8][kc]);
                af[mt][2] = __float_as_uint(As[r][kc + 4]);
                af[mt][3] = __float_as_uint(As[r + 8][kc + 4]);
            }
            unsigned bf[4][2];
#pragma unroll
            for (int nt = 0; nt < 4; nt++) {
                const int n = wn + nt * 8 + qr;
                bf[nt][0] = __float_as_uint(Ws[n][kc]);
                bf[nt][1] = __float_as_uint(Ws[n][kc + 4]);
            }
#pragma unroll
            for (int mt = 0; mt < 4; mt++)
#pragma unroll
                for (int nt = 0; nt < 4; nt++)
                    mma_tf32(acc[mt][nt][0], acc[mt][nt][1],
                             acc[mt][nt][2], acc[mt][nt][3],
                             af[mt][0], af[mt][1], af[mt][2], af[mt][3],
                             bf[nt][0], bf[nt][1]);
        }
    }

    // epilogue: bias + store (C frag: rows qr, qr+8; cols 2*qc, 2*qc+1)
#pragma unroll
    for (int nt = 0; nt < 4; nt++) {
        const int col = bn + wn + nt * 8 + 2 * qc;
        const float2 bv = *(const float2*)(bias + col);
#pragma unroll
        for (int mt = 0; mt < 4; mt++) {
            const int r0 = bm + wm + mt * 16 + qr;
            float2 v0 = make_float2(acc[mt][nt][0] + bv.x, acc[mt][nt][1] + bv.y);
            float2 v1 = make_float2(acc[mt][nt][2] + bv.x, acc[mt][nt][3] + bv.y);
            *(float2*)(C + (size_t)r0 * N + col)       = v0;
            *(float2*)(C + (size_t)(r0 + 8) * N + col) = v1;
        }
    }
}

// ---------------------------------------------------------------------------
// Flash attention with tf32 mma. Block = 64 queries of one (b,h).
// 128 threads = 4 warps; warp w owns query rows [16w, 16w+16).
// Smem strides chosen for conflict-free fragment access:
//   Qs/Ks/Ps stride 68 (A-frag & K B-frag pattern 4r+j distinct)
//   Vs stride 72       (V B-frag pattern 8j+r distinct)
// ---------------------------------------------------------------------------
#define QSTR 68
#define KSTR 68
#define VSTR 72
#define PSTR 68

__global__ __launch_bounds__(128) void attn_tf32(
    const float* __restrict__ qkv, float* __restrict__ out)
{
    extern __shared__ float smem[];
    float* Qs = smem;                       // 64*68
    float* Ks = Qs + 64 * QSTR;             // 64*68
    float* Vs = Ks + 64 * KSTR;             // 64*72
    float* Ps = Vs + 64 * VSTR;             // 64*68 (per-warp 16-row slices)

    const int bh = blockIdx.y;
    const int b  = bh >> 4;
    const int h  = bh & 15;
    const int q0 = blockIdx.x * 64;

    const int tid  = threadIdx.x;
    const int lane = tid & 31;
    const int wid  = tid >> 5;
    const int wrow = wid * 16;
    const int qr = lane >> 2;   // 0..7
    const int qc = lane & 3;    // 0..3

    const float* base = qkv + (size_t)b * T_SZ * D3;
    const int hoff = h * DHEAD;

    // Load Q tile (64x64) -> tf32 smem
#pragma unroll
    for (int i = 0; i < 8; i++) {
        const int fidx = tid + i * 128;       // 0..1023
        const int row = fidx >> 4;
        const int d4  = fidx & 15;
        float4 v = *(const float4*)(base + (size_t)(q0 + row) * D3 + hoff + d4 * 4);
        float* dst = &Qs[row * QSTR + d4 * 4];
        dst[0] = __uint_as_float(f2tf(v.x));
        dst[1] = __uint_as_float(f2tf(v.y));
        dst[2] = __uint_as_float(f2tf(v.z));
        dst[3] = __uint_as_float(f2tf(v.w));
    }

    float miA = -INFINITY, miB = -INFINITY;
    float lA = 0.f, lB = 0.f;
    float oacc[8][4];
#pragma unroll
    for (int nt = 0; nt < 8; nt++)
#pragma unroll
        for (int r = 0; r < 4; r++) oacc[nt][r] = 0.f;

    for (int kt = 0; kt < T_SZ / 64; kt++) {
        const int k0 = kt * 64;
        __syncthreads();   // all warps done with previous Ks/Vs (and Q visible)
#pragma unroll
        for (int i = 0; i < 8; i++) {
            const int fidx = tid + i * 128;
            const int row = fidx >> 4;
            const int d4  = fidx & 15;
            const float* rp = base + (size_t)(k0 + row) * D3 + hoff + d4 * 4;
            float4 kv = *(const float4*)(rp + D_MODEL);
            float4 vv = *(const float4*)(rp + 2 * D_MODEL);
            float* kd = &Ks[row * KSTR + d4 * 4];
            kd[0] = __uint_as_float(f2tf(kv.x));
            kd[1] = __uint_as_float(f2tf(kv.y));
            kd[2] = __uint_as_float(f2tf(kv.z));
            kd[3] = __uint_as_float(f2tf(kv.w));
            float* vd = &Vs[row * VSTR + d4 * 4];
            vd[0] = __uint_as_float(f2tf(vv.x));
            vd[1] = __uint_as_float(f2tf(vv.y));
            vd[2] = __uint_as_float(f2tf(vv.z));
            vd[3] = __uint_as_float(f2tf(vv.w));
        }
        __syncthreads();

        // ---- S = Q K^T : warp computes 16x64 via 8 ksteps x 8 ntiles ----
        float sacc[8][4];
#pragma unroll
        for (int nt = 0; nt < 8; nt++)
#pragma unroll
            for (int r = 0; r < 4; r++) sacc[nt][r] = 0.f;

#pragma unroll
        for (int ks = 0; ks < 8; ks++) {
            const int kc = ks * 8 + qc;
            const unsigned a0 = __float_as_uint(Qs[(wrow + qr) * QSTR + kc]);
            const unsigned a1 = __float_as_uint(Qs[(wrow + qr + 8) * QSTR + kc]);
            const unsigned a2 = __float_as_uint(Qs[(wrow + qr) * QSTR + kc + 4]);
            const unsigned a3 = __float_as_uint(Qs[(wrow + qr + 8) * QSTR + kc + 4]);
#pragma unroll
            for (int nt = 0; nt < 8; nt++) {
                const unsigned b0 = __float_as_uint(Ks[(nt * 8 + qr) * KSTR + kc]);
                const unsigned b1 = __float_as_uint(Ks[(nt * 8 + qr) * KSTR + kc + 4]);
                mma_tf32(sacc[nt][0], sacc[nt][1], sacc[nt][2], sacc[nt][3],
                         a0, a1, a2, a3, b0, b1);
            }
        }

        // ---- online softmax (rows: A = wrow+qr, B = wrow+qr+8) ----
        const float scale = 0.125f;
        float mA = -INFINITY, mB = -INFINITY;
#pragma unroll
        for (int nt = 0; nt < 8; nt++) {
            sacc[nt][0] *= scale; sacc[nt][1] *= scale;
            sacc[nt][2] *= scale; sacc[nt][3] *= scale;
            mA = fmaxf(mA, fmaxf(sacc[nt][0], sacc[nt][1]));
            mB = fmaxf(mB, fmaxf(sacc[nt][2], sacc[nt][3]));
        }
        mA = fmaxf(mA, __shfl_xor_sync(0xffffffffu, mA, 1));
        mA = fmaxf(mA, __shfl_xor_sync(0xffffffffu, mA, 2));
        mB = fmaxf(mB, __shfl_xor_sync(0xffffffffu, mB, 1));
        mB = fmaxf(mB, __shfl_xor_sync(0xffffffffu, mB, 2));
        const float mnA = fmaxf(miA, mA);
        const float mnB = fmaxf(miB, mB);
        const float corrA = __expf(miA - mnA);
        const float corrB = __expf(miB - mnB);

        float psA = 0.f, psB = 0.f;
        const int prA = (wrow + qr) * PSTR;
        const int prB = (wrow + qr + 8) * PSTR;
#pragma unroll
        for (int nt = 0; nt < 8; nt++) {
            const int col = nt * 8 + 2 * qc;
            float p0 = __expf(sacc[nt][0] - mnA);
            float p1 = __expf(sacc[nt][1] - mnA);
            float p2 = __expf(sacc[nt][2] - mnB);
            float p3 = __expf(sacc[nt][3] - mnB);
            psA += p0 + p1;
            psB += p2 + p3;
            *(float2*)(&Ps[prA + col]) =
                make_float2(__uint_as_float(f2tf(p0)), __uint_as_float(f2tf(p1)));
            *(float2*)(&Ps[prB + col]) =
                make_float2(__uint_as_float(f2tf(p2)), __uint_as_float(f2tf(p3)));
        }
        psA += __shfl_xor_sync(0xffffffffu, psA, 1);
        psA += __shfl_xor_sync(0xffffffffu, psA, 2);
        psB += __shfl_xor_sync(0xffffffffu, psB, 1);
        psB += __shfl_xor_sync(0xffffffffu, psB, 2);
        lA = lA * corrA + psA;
        lB = lB * corrB + psB;
        miA = mnA; miB = mnB;

#pragma unroll
        for (int nt = 0; nt < 8; nt++) {
            oacc[nt][0] *= corrA; oacc[nt][1] *= corrA;
            oacc[nt][2] *= corrB; oacc[nt][3] *= corrB;
        }
        __syncwarp();   // Ps slice written by this warp before reading as A-frags

        // ---- O += P V : 8 ksteps x 8 ntiles ----
#pragma unroll
        for (int ks = 0; ks < 8; ks++) {
            const int kc = ks * 8 + qc;
            const unsigned a0 = __float_as_uint(Ps[(wrow + qr) * PSTR + kc]);
            const unsigned a1 = __float_as_uint(Ps[(wrow + qr + 8) * PSTR + kc]);
            const unsigned a2 = __float_as_uint(Ps[(wrow + qr) * PSTR + kc + 4]);
            const unsigned a3 = __float_as_uint(Ps[(wrow + qr + 8) * PSTR + kc + 4]);
#pragma unroll
            for (int nt = 0; nt < 8; nt++) {
                const unsigned b0 = __float_as_uint(Vs[(ks * 8 + qc) * VSTR + nt * 8 + qr]);
                const unsigned b1 = __float_as_uint(Vs[(ks * 8 + qc + 4) * VSTR + nt * 8 + qr]);
                mma_tf32(oacc[nt][0], oacc[nt][1], oacc[nt][2], oacc[nt][3],
                         a0, a1, a2, a3, b0, b1);
            }
        }
    }

    // epilogue
    const float invA = 1.f / lA;
    const float invB = 1.f / lB;
    const int rowA = q0 + wrow + qr;
    float* opA = out + (size_t)(b * T_SZ + rowA) * D_MODEL + hoff;
    float* opB = opA + (size_t)8 * D_MODEL;
#pragma unroll
    for (int nt = 0; nt < 8; nt++) {
        const int col = nt * 8 + 2 * qc;
        *(float2*)(opA + col) = make_float2(oacc[nt][0] * invA, oacc[nt][1] * invA);
        *(float2*)(opB + col) = make_float2(oacc[nt][2] * invB, oacc[nt][3] * invB);
    }
}

// ---------------------------------------------------------------------------
// Launch
// ---------------------------------------------------------------------------
extern "C" void kernel_launch(void* const* d_in, const int* in_sizes, int n_in,
                              void* d_out, int out_size)
{
    const float* x     = (const float*)d_in[0];
    const float* qkv_w = (const float*)d_in[1];
    const float* qkv_b = (const float*)d_in[2];
    const float* out_w = (const float*)d_in[3];
    const float* out_b = (const float*)d_in[4];
    float* out = (float*)d_out;

    float *qkvbuf, *attbuf;
    cudaGetSymbolAddress((void**)&qkvbuf, g_qkv);
    cudaGetSymbolAddress((void**)&attbuf, g_att);

    const int attn_smem = 64 * (QSTR + KSTR + VSTR + PSTR) * (int)sizeof(float);
    cudaFuncSetAttribute(attn_tf32, cudaFuncAttributeMaxDynamicSharedMemorySize,
                         attn_smem);

    // 1) QKV projection: [8192,1024] @ [3072,1024]^T + b -> [8192,3072]
    gemm_tf32<<<dim3(D3 / BN, MROWS / BM), 256>>>(
        x, qkv_w, qkv_b, qkvbuf, MROWS, D3, D_MODEL);

    // 2) Attention: 64 (b,h) pairs x 32 query tiles
    attn_tf32<<<dim3(T_SZ / 64, B_SZ * NHEAD), 128, attn_smem>>>(qkvbuf, attbuf);

    // 3) Output projection: [8192,1024] @ [1024,1024]^T + b -> [8192,1024]
    gemm_tf32<<<dim3(D_MODEL / BN, MROWS / BM), 256>>>(
        attbuf, out_w, out_b, out, MROWS, D_MODEL, D_MODEL);
}

// round 7
// speedup vs baseline: 6.6606x; 1.2062x over previous
#include <cuda_runtime.h>
#include <cuda_bf16.h>
#include <math.h>

// Problem constants
#define B_SZ    4
#define T_SZ    2048
#define D_MODEL 1024
#define NHEAD   16
#define DHEAD   64
#define D3      (3 * D_MODEL)
#define MROWS   (B_SZ * T_SZ)          // 8192

// Scratch (static device globals — allocation-free per harness rules)
__device__ float g_qkv[(size_t)MROWS * D3];      // [8192, 3072]
__device__ float g_att[(size_t)MROWS * D_MODEL]; // [8192, 1024]

// ---------------------------------------------------------------------------
// Helpers
// ---------------------------------------------------------------------------
__device__ __forceinline__ unsigned f2tf(float x) {
    unsigned r;
    asm("cvt.rna.tf32.f32 %0, %1;" : "=r"(r) : "f"(x));
    return r;
}

__device__ __forceinline__ void mma_tf32(
    float& d0, float& d1, float& d2, float& d3,
    unsigned a0, unsigned a1, unsigned a2, unsigned a3,
    unsigned b0, unsigned b1)
{
    asm("mma.sync.aligned.m16n8k8.row.col.f32.tf32.tf32.f32 "
        "{%0,%1,%2,%3}, {%4,%5,%6,%7}, {%8,%9}, {%0,%1,%2,%3};"
        : "+f"(d0), "+f"(d1), "+f"(d2), "+f"(d3)
        : "r"(a0), "r"(a1), "r"(a2), "r"(a3), "r"(b0), "r"(b1));
}

__device__ __forceinline__ void cp_async16(void* smem_dst, const void* gsrc) {
    unsigned saddr = (unsigned)__cvta_generic_to_shared(smem_dst);
    asm volatile("cp.async.ca.shared.global [%0], [%1], 16;"
                 :: "r"(saddr), "l"(gsrc));
}
#define CP_COMMIT()  asm volatile("cp.async.commit_group;")
#define CP_WAIT1()   asm volatile("cp.async.wait_group 1;")

// ---------------------------------------------------------------------------
// TF32 GEMM v2: C[M,N] = A[M,K] @ W[N,K]^T + bias[N]
// 128x128x16 block, 128 threads (4 warps 2x2), warp tile 64x64 (4x8 mmas).
// cp.async 2-stage double buffer. Smem row stride 36 floats:
//   - 144B rows -> 16B aligned for cp.async
//   - fragment LDS addr (36*qr + qc) mod 32 = 4qr+qc -> conflict-free
// tf32 by truncation (tensor core ignores low mantissa bits).
// ---------------------------------------------------------------------------
#define GBM 128
#define GBN 128
#define GBK 16
#define GSTR 36
#define GEMM_SMEM (2 * (GBM + GBN) * GSTR * 4)   // 73728 bytes

__global__ __launch_bounds__(128) void gemm_tf32_v2(
    const float* __restrict__ A, const float* __restrict__ W,
    const float* __restrict__ bias, float* __restrict__ C,
    int M, int N, int K)
{
    extern __shared__ float dsm[];
    float* As = dsm;                       // [2][128][36]
    float* Ws = dsm + 2 * GBM * GSTR;      // [2][128][36]

    const int tid  = threadIdx.x;
    const int lane = tid & 31;
    const int wid  = tid >> 5;
    const int wm = (wid >> 1) * 64;        // 0 or 64
    const int wn = (wid & 1) * 64;         // 0 or 64
    const int bm = blockIdx.y * GBM;
    const int bn = blockIdx.x * GBN;
    const int qr = lane >> 2;              // 0..7
    const int qc = lane & 3;               // 0..3

    const float* Abase = A + (size_t)bm * K;
    const float* Wbase = W + (size_t)bn * K;

    float acc[4][8][4];
#pragma unroll
    for (int mt = 0; mt < 4; mt++)
#pragma unroll
        for (int nt = 0; nt < 8; nt++)
#pragma unroll
            for (int r = 0; r < 4; r++) acc[mt][nt][r] = 0.f;

    const int NIT = K / GBK;   // 64

    // preload stage 0
    {
#pragma unroll
        for (int i = 0; i < 4; i++) {
            const int cid = tid + i * 128;          // 0..511
            const int row = cid >> 2;
            const int c4  = (cid & 3) * 4;
            cp_async16(&As[row * GSTR + c4], Abase + (size_t)row * K + c4);
            cp_async16(&Ws[row * GSTR + c4], Wbase + (size_t)row * K + c4);
        }
        CP_COMMIT();
    }

    for (int it = 0; it < NIT; it++) {
        const int s = it & 1;
        __syncthreads();   // all warps done computing stage 1-s (prev iter)
        if (it + 1 < NIT) {
            const int k0 = (it + 1) * GBK;
            const int so = (1 - s) * GBM * GSTR;
#pragma unroll
            for (int i = 0; i < 4; i++) {
                const int cid = tid + i * 128;
                const int row = cid >> 2;
                const int c4  = (cid & 3) * 4;
                cp_async16(&As[so + row * GSTR + c4],
                           Abase + (size_t)row * K + k0 + c4);
                cp_async16(&Ws[so + row * GSTR + c4],
                           Wbase + (size_t)row * K + k0 + c4);
            }
        }
        CP_COMMIT();
        CP_WAIT1();        // stage s data arrived (only newest group pending)
        __syncthreads();

        const int so = s * GBM * GSTR;
#pragma unroll
        for (int ks = 0; ks < 2; ks++) {
            const int kc = ks * 8 + qc;
            unsigned af[4][4];
#pragma unroll
            for (int mt = 0; mt < 4; mt++) {
                const int r = wm + mt * 16 + qr;
                af[mt][0] = __float_as_uint(As[so + r * GSTR + kc]);
                af[mt][1] = __float_as_uint(As[so + (r + 8) * GSTR + kc]);
                af[mt][2] = __float_as_uint(As[so + r * GSTR + kc + 4]);
                af[mt][3] = __float_as_uint(As[so + (r + 8) * GSTR + kc + 4]);
            }
            unsigned bf[8][2];
#pragma unroll
            for (int nt = 0; nt < 8; nt++) {
                const int n = wn + nt * 8 + qr;
                bf[nt][0] = __float_as_uint(Ws[so + n * GSTR + kc]);
                bf[nt][1] = __float_as_uint(Ws[so + n * GSTR + kc + 4]);
            }
#pragma unroll
            for (int mt = 0; mt < 4; mt++)
#pragma unroll
                for (int nt = 0; nt < 8; nt++)
                    mma_tf32(acc[mt][nt][0], acc[mt][nt][1],
                             acc[mt][nt][2], acc[mt][nt][3],
                             af[mt][0], af[mt][1], af[mt][2], af[mt][3],
                             bf[nt][0], bf[nt][1]);
        }
    }

    // epilogue: bias + float2 stores
#pragma unroll
    for (int nt = 0; nt < 8; nt++) {
        const int col = bn + wn + nt * 8 + 2 * qc;
        const float2 bv = *(const float2*)(bias + col);
#pragma unroll
        for (int mt = 0; mt < 4; mt++) {
            const int r0 = bm + wm + mt * 16 + qr;
            float2 v0 = make_float2(acc[mt][nt][0] + bv.x, acc[mt][nt][1] + bv.y);
            float2 v1 = make_float2(acc[mt][nt][2] + bv.x, acc[mt][nt][3] + bv.y);
            *(float2*)(C + (size_t)r0 * N + col)       = v0;
            *(float2*)(C + (size_t)(r0 + 8) * N + col) = v1;
        }
    }
}

// ---------------------------------------------------------------------------
// Flash attention v2: 128-query tile, 4 warps, warp tile 32x64 (mt=2, nt=8).
// Same verified strides as R5: Q/K/P stride 68 (4qr+qc conflict-free),
// V stride 72 (8qc+qr conflict-free B-frag loads).
// ---------------------------------------------------------------------------
#define AQ   128
#define QSTR 68
#define KSTR 68
#define VSTR 72
#define PSTR 68
#define ATT_SMEM ((AQ * QSTR + 64 * KSTR + 64 * VSTR + AQ * PSTR) * 4)  // 105472

__global__ __launch_bounds__(128) void attn_tf32_v2(
    const float* __restrict__ qkv, float* __restrict__ out)
{
    extern __shared__ float smem[];
    float* Qs = smem;                        // 128*68
    float* Ks = Qs + AQ * QSTR;              // 64*68
    float* Vs = Ks + 64 * KSTR;              // 64*72
    float* Ps = Vs + 64 * VSTR;              // 128*68

    const int bh = blockIdx.y;
    const int b  = bh >> 4;
    const int h  = bh & 15;
    const int q0 = blockIdx.x * AQ;

    const int tid  = threadIdx.x;
    const int lane = tid & 31;
    const int wid  = tid >> 5;
    const int wrow = wid * 32;               // warp owns 32 query rows
    const int qr = lane >> 2;
    const int qc = lane & 3;

    const float* base = qkv + (size_t)b * T_SZ * D3;
    const int hoff = h * DHEAD;

    // Load Q tile (128 x 64) -> tf32 smem (rna)
#pragma unroll
    for (int i = 0; i < 16; i++) {
        const int fidx = tid + i * 128;        // 0..2047
        const int row = fidx >> 4;
        const int d4  = fidx & 15;
        float4 v = *(const float4*)(base + (size_t)(q0 + row) * D3 + hoff + d4 * 4);
        float* dst = &Qs[row * QSTR + d4 * 4];
        dst[0] = __uint_as_float(f2tf(v.x));
        dst[1] = __uint_as_float(f2tf(v.y));
        dst[2] = __uint_as_float(f2tf(v.z));
        dst[3] = __uint_as_float(f2tf(v.w));
    }

    // softmax state per (mt, half): rows wrow+mt*16+qr (A) and +8 (B)
    float mi[2][2], li[2][2];
#pragma unroll
    for (int mt = 0; mt < 2; mt++) {
        mi[mt][0] = -INFINITY; mi[mt][1] = -INFINITY;
        li[mt][0] = 0.f;       li[mt][1] = 0.f;
    }
    float oacc[2][8][4];
#pragma unroll
    for (int mt = 0; mt < 2; mt++)
#pragma unroll
        for (int nt = 0; nt < 8; nt++)
#pragma unroll
            for (int r = 0; r < 4; r++) oacc[mt][nt][r] = 0.f;

    for (int kt = 0; kt < T_SZ / 64; kt++) {
        const int k0 = kt * 64;
        __syncthreads();   // all warps done with previous Ks/Vs; Q visible
#pragma unroll
        for (int i = 0; i < 8; i++) {
            const int fidx = tid + i * 128;     // 0..1023
            const int row = fidx >> 4;
            const int d4  = fidx & 15;
            const float* rp = base + (size_t)(k0 + row) * D3 + hoff + d4 * 4;
            float4 kv = *(const float4*)(rp + D_MODEL);
            float4 vv = *(const float4*)(rp + 2 * D_MODEL);
            float* kd = &Ks[row * KSTR + d4 * 4];
            kd[0] = __uint_as_float(f2tf(kv.x));
            kd[1] = __uint_as_float(f2tf(kv.y));
            kd[2] = __uint_as_float(f2tf(kv.z));
            kd[3] = __uint_as_float(f2tf(kv.w));
            float* vd = &Vs[row * VSTR + d4 * 4];
            vd[0] = __uint_as_float(f2tf(vv.x));
            vd[1] = __uint_as_float(f2tf(vv.y));
            vd[2] = __uint_as_float(f2tf(vv.z));
            vd[3] = __uint_as_float(f2tf(vv.w));
        }
        __syncthreads();

        // ---- S = Q K^T : warp computes 32x64 (mt2 x nt8 x ks8) ----
        float sacc[2][8][4];
#pragma unroll
        for (int mt = 0; mt < 2; mt++)
#pragma unroll
            for (int nt = 0; nt < 8; nt++)
#pragma unroll
                for (int r = 0; r < 4; r++) sacc[mt][nt][r] = 0.f;

#pragma unroll
        for (int ks = 0; ks < 8; ks++) {
            const int kc = ks * 8 + qc;
            unsigned af[2][4];
#pragma unroll
            for (int mt = 0; mt < 2; mt++) {
                const int R = wrow + mt * 16 + qr;
                af[mt][0] = __float_as_uint(Qs[R * QSTR + kc]);
                af[mt][1] = __float_as_uint(Qs[(R + 8) * QSTR + kc]);
                af[mt][2] = __float_as_uint(Qs[R * QSTR + kc + 4]);
                af[mt][3] = __float_as_uint(Qs[(R + 8) * QSTR + kc + 4]);
            }
#pragma unroll
            for (int nt = 0; nt < 8; nt++) {
                const int n = nt * 8 + qr;
                const unsigned b0 = __float_as_uint(Ks[n * KSTR + kc]);
                const unsigned b1 = __float_as_uint(Ks[n * KSTR + kc + 4]);
#pragma unroll
                for (int mt = 0; mt < 2; mt++)
                    mma_tf32(sacc[mt][nt][0], sacc[mt][nt][1],
                             sacc[mt][nt][2], sacc[mt][nt][3],
                             af[mt][0], af[mt][1], af[mt][2], af[mt][3],
                             b0, b1);
            }
        }

        // ---- online softmax per mt ----
        const float scale = 0.125f;
#pragma unroll
        for (int mt = 0; mt < 2; mt++) {
            float mA = -INFINITY, mB = -INFINITY;
#pragma unroll
            for (int nt = 0; nt < 8; nt++) {
                sacc[mt][nt][0] *= scale; sacc[mt][nt][1] *= scale;
                sacc[mt][nt][2] *= scale; sacc[mt][nt][3] *= scale;
                mA = fmaxf(mA, fmaxf(sacc[mt][nt][0], sacc[mt][nt][1]));
                mB = fmaxf(mB, fmaxf(sacc[mt][nt][2], sacc[mt][nt][3]));
            }
            mA = fmaxf(mA, __shfl_xor_sync(0xffffffffu, mA, 1));
            mA = fmaxf(mA, __shfl_xor_sync(0xffffffffu, mA, 2));
            mB = fmaxf(mB, __shfl_xor_sync(0xffffffffu, mB, 1));
            mB = fmaxf(mB, __shfl_xor_sync(0xffffffffu, mB, 2));
            const float mnA = fmaxf(mi[mt][0], mA);
            const float mnB = fmaxf(mi[mt][1], mB);
            const float corrA = __expf(mi[mt][0] - mnA);
            const float corrB = __expf(mi[mt][1] - mnB);

            float psA = 0.f, psB = 0.f;
            const int prA = (wrow + mt * 16 + qr) * PSTR;
            const int prB = (wrow + mt * 16 + qr + 8) * PSTR;
#pragma unroll
            for (int nt = 0; nt < 8; nt++) {
                const int col = nt * 8 + 2 * qc;
                // rna-convert, then sum the converted values so l matches P
                float p0 = __uint_as_float(f2tf(__expf(sacc[mt][nt][0] - mnA)));
                float p1 = __uint_as_float(f2tf(__expf(sacc[mt][nt][1] - mnA)));
                float p2 = __uint_as_float(f2tf(__expf(sacc[mt][nt][2] - mnB)));
                float p3 = __uint_as_float(f2tf(__expf(sacc[mt][nt][3] - mnB)));
                psA += p0 + p1;
                psB += p2 + p3;
                *(float2*)(&Ps[prA + col]) = make_float2(p0, p1);
                *(float2*)(&Ps[prB + col]) = make_float2(p2, p3);
            }
            psA += __shfl_xor_sync(0xffffffffu, psA, 1);
            psA += __shfl_xor_sync(0xffffffffu, psA, 2);
            psB += __shfl_xor_sync(0xffffffffu, psB, 1);
            psB += __shfl_xor_sync(0xffffffffu, psB, 2);
            li[mt][0] = li[mt][0] * corrA + psA;
            li[mt][1] = li[mt][1] * corrB + psB;
            mi[mt][0] = mnA; mi[mt][1] = mnB;

#pragma unroll
            for (int nt = 0; nt < 8; nt++) {
                oacc[mt][nt][0] *= corrA; oacc[mt][nt][1] *= corrA;
                oacc[mt][nt][2] *= corrB; oacc[mt][nt][3] *= corrB;
            }
        }
        __syncwarp();   // this warp's Ps rows written before A-frag reads

        // ---- O += P V ----
#pragma unroll
        for (int ks = 0; ks < 8; ks++) {
            const int kc = ks * 8 + qc;
            unsigned af[2][4];
#pragma unroll
            for (int mt = 0; mt < 2; mt++) {
                const int R = wrow + mt * 16 + qr;
                af[mt][0] = __float_as_uint(Ps[R * PSTR + kc]);
                af[mt][1] = __float_as_uint(Ps[(R + 8) * PSTR + kc]);
                af[mt][2] = __float_as_uint(Ps[R * PSTR + kc + 4]);
                af[mt][3] = __float_as_uint(Ps[(R + 8) * PSTR + kc + 4]);
            }
#pragma unroll
            for (int nt = 0; nt < 8; nt++) {
                const unsigned b0 = __float_as_uint(Vs[(ks * 8 + qc) * VSTR + nt * 8 + qr]);
                const unsigned b1 = __float_as_uint(Vs[(ks * 8 + qc + 4) * VSTR + nt * 8 + qr]);
#pragma unroll
                for (int mt = 0; mt < 2; mt++)
                    mma_tf32(oacc[mt][nt][0], oacc[mt][nt][1],
                             oacc[mt][nt][2], oacc[mt][nt][3],
                             af[mt][0], af[mt][1], af[mt][2], af[mt][3],
                             b0, b1);
            }
        }
    }

    // epilogue
#pragma unroll
    for (int mt = 0; mt < 2; mt++) {
        const float invA = 1.f / li[mt][0];
        const float invB = 1.f / li[mt][1];
        const int rowA = q0 + wrow + mt * 16 + qr;
        float* opA = out + (size_t)(b * T_SZ + rowA) * D_MODEL + hoff;
        float* opB = opA + (size_t)8 * D_MODEL;
#pragma unroll
        for (int nt = 0; nt < 8; nt++) {
            const int col = nt * 8 + 2 * qc;
            *(float2*)(opA + col) = make_float2(oacc[mt][nt][0] * invA,
                                                oacc[mt][nt][1] * invA);
            *(float2*)(opB + col) = make_float2(oacc[mt][nt][2] * invB,
                                                oacc[mt][nt][3] * invB);
        }
    }
}

// ---------------------------------------------------------------------------
// Launch
// ---------------------------------------------------------------------------
extern "C" void kernel_launch(void* const* d_in, const int* in_sizes, int n_in,
                              void* d_out, int out_size)
{
    const float* x     = (const float*)d_in[0];
    const float* qkv_w = (const float*)d_in[1];
    const float* qkv_b = (const float*)d_in[2];
    const float* out_w = (const float*)d_in[3];
    const float* out_b = (const float*)d_in[4];
    float* out = (float*)d_out;

    float *qkvbuf, *attbuf;
    cudaGetSymbolAddress((void**)&qkvbuf, g_qkv);
    cudaGetSymbolAddress((void**)&attbuf, g_att);

    cudaFuncSetAttribute(gemm_tf32_v2, cudaFuncAttributeMaxDynamicSharedMemorySize,
                         GEMM_SMEM);
    cudaFuncSetAttribute(attn_tf32_v2, cudaFuncAttributeMaxDynamicSharedMemorySize,
                         ATT_SMEM);

    // 1) QKV projection: [8192,1024] @ [3072,1024]^T + b -> [8192,3072]
    gemm_tf32_v2<<<dim3(D3 / GBN, MROWS / GBM), 128, GEMM_SMEM>>>(
        x, qkv_w, qkv_b, qkvbuf, MROWS, D3, D_MODEL);

    // 2) Attention: 64 (b,h) pairs x 16 query tiles of 128
    attn_tf32_v2<<<dim3(T_SZ / AQ, B_SZ * NHEAD), 128, ATT_SMEM>>>(qkvbuf, attbuf);

    // 3) Output projection: [8192,1024] @ [1024,1024]^T + b -> [8192,1024]
    gemm_tf32_v2<<<dim3(D_MODEL / GBN, MROWS / GBM), 128, GEMM_SMEM>>>(
        attbuf, out_w, out_b, out, MROWS, D_MODEL, D_MODEL);
}

// round 8
// speedup vs baseline: 8.0504x; 1.2087x over previous
#include <cuda_runtime.h>
#include <cuda_bf16.h>
#include <math.h>

// Problem constants
#define B_SZ    4
#define T_SZ    2048
#define D_MODEL 1024
#define NHEAD   16
#define DHEAD   64
#define D3      (3 * D_MODEL)
#define MROWS   (B_SZ * T_SZ)          // 8192

// Scratch (static device globals — allocation-free per harness rules)
__device__ float g_qkv[(size_t)MROWS * D3];      // [8192, 3072]
__device__ float g_att[(size_t)MROWS * D_MODEL]; // [8192, 1024]
__device__ float g_xc[(size_t)MROWS * D_MODEL];  // tf32-rna copy of x
__device__ float g_wq[(size_t)D3 * D_MODEL];     // tf32-rna copy of qkv_w
__device__ float g_wo[(size_t)D_MODEL * D_MODEL];// tf32-rna copy of out_w

// ---------------------------------------------------------------------------
// Helpers
// ---------------------------------------------------------------------------
__device__ __forceinline__ unsigned f2tf(float x) {
    unsigned r;
    asm("cvt.rna.tf32.f32 %0, %1;" : "=r"(r) : "f"(x));
    return r;
}

__device__ __forceinline__ void mma_tf32(
    float& d0, float& d1, float& d2, float& d3,
    unsigned a0, unsigned a1, unsigned a2, unsigned a3,
    unsigned b0, unsigned b1)
{
    asm("mma.sync.aligned.m16n8k8.row.col.f32.tf32.tf32.f32 "
        "{%0,%1,%2,%3}, {%4,%5,%6,%7}, {%8,%9}, {%0,%1,%2,%3};"
        : "+f"(d0), "+f"(d1), "+f"(d2), "+f"(d3)
        : "r"(a0), "r"(a1), "r"(a2), "r"(a3), "r"(b0), "r"(b1));
}

#define LDSM4(r0, r1, r2, r3, addr) \
    asm volatile("ldmatrix.sync.aligned.m8n8.x4.shared.b16 {%0,%1,%2,%3}, [%4];" \
                 : "=r"(r0), "=r"(r1), "=r"(r2), "=r"(r3) : "r"(addr))

__device__ __forceinline__ void cp_async16(void* smem_dst, const void* gsrc) {
    unsigned saddr = (unsigned)__cvta_generic_to_shared(smem_dst);
    asm volatile("cp.async.ca.shared.global [%0], [%1], 16;"
                 :: "r"(saddr), "l"(gsrc));
}
#define CP_COMMIT()  asm volatile("cp.async.commit_group;")
#define CP_WAIT1()   asm volatile("cp.async.wait_group 1;")

// ---------------------------------------------------------------------------
// Pre-pass: round fp32 array to tf32 (rna) so cp.async truncation is lossless.
// ---------------------------------------------------------------------------
__global__ __launch_bounds__(256) void cvt_tf32_rna(
    const float* __restrict__ in, float* __restrict__ out, int n4)
{
    int i = blockIdx.x * blockDim.x + threadIdx.x;
    if (i < n4) {
        float4 v = ((const float4*)in)[i];
        v.x = __uint_as_float(f2tf(v.x));
        v.y = __uint_as_float(f2tf(v.y));
        v.z = __uint_as_float(f2tf(v.z));
        v.w = __uint_as_float(f2tf(v.w));
        ((float4*)out)[i] = v;
    }
}

// ---------------------------------------------------------------------------
// TF32 GEMM v3: C[M,N] = A[M,K] @ W[N,K]^T + bias[N]
// 128x128x16 block, 128 threads (4 warps 2x2), warp tile 64x64 (4x8 mmas).
// cp.async 2-stage double buffer; ldmatrix.x4 fragment loads.
// Smem row stride 36 floats (144B): 16B-aligned rows, 36 mod 32 = 4 ->
// each ldmatrix matrix's 8 rows cover all 32 banks exactly once.
// Inputs are pre-rounded to tf32-rna in gmem.
// ---------------------------------------------------------------------------
#define GBM 128
#define GBN 128
#define GBK 16
#define GSTR 36
#define GEMM_SMEM (2 * (GBM + GBN) * GSTR * 4)   // 73728 bytes

__global__ __launch_bounds__(128) void gemm_tf32_v3(
    const float* __restrict__ A, const float* __restrict__ W,
    const float* __restrict__ bias, float* __restrict__ C,
    int M, int N, int K)
{
    extern __shared__ float dsm[];
    float* As = dsm;                       // [2][128][36]
    float* Ws = dsm + 2 * GBM * GSTR;      // [2][128][36]

    const int tid  = threadIdx.x;
    const int lane = tid & 31;
    const int wid  = tid >> 5;
    const int wm = (wid >> 1) * 64;        // 0 or 64
    const int wn = (wid & 1) * 64;         // 0 or 64
    const int bm = blockIdx.y * GBM;
    const int bn = blockIdx.x * GBN;
    const int qr = lane >> 2;              // 0..7
    const int qc = lane & 3;               // 0..3

    // ldmatrix per-lane row-address components
    const int arow = (lane & 7) + 8 * ((lane >> 3) & 1);
    const int acol = 4 * (lane >> 4);
    const int brow = (lane & 7) + 8 * (lane >> 4);
    const int bcol = 4 * ((lane >> 3) & 1);

    const unsigned As_u = (unsigned)__cvta_generic_to_shared(As);
    const unsigned Ws_u = (unsigned)__cvta_generic_to_shared(Ws);
    unsigned a_ad[4], b_ad[4];
#pragma unroll
    for (int mt = 0; mt < 4; mt++)
        a_ad[mt] = As_u + ((wm + mt * 16 + arow) * GSTR + acol) * 4u;
#pragma unroll
    for (int p = 0; p < 4; p++)
        b_ad[p] = Ws_u + ((wn + p * 16 + brow) * GSTR + bcol) * 4u;

    const float* Abase = A + (size_t)bm * K;
    const float* Wbase = W + (size_t)bn * K;

    float acc[4][8][4];
#pragma unroll
    for (int mt = 0; mt < 4; mt++)
#pragma unroll
        for (int nt = 0; nt < 8; nt++)
#pragma unroll
            for (int r = 0; r < 4; r++) acc[mt][nt][r] = 0.f;

    const int NIT = K / GBK;   // 64

    // preload stage 0
    {
#pragma unroll
        for (int i = 0; i < 4; i++) {
            const int cid = tid + i * 128;          // 0..511
            const int row = cid >> 2;
            const int c4  = (cid & 3) * 4;
            cp_async16(&As[row * GSTR + c4], Abase + (size_t)row * K + c4);
            cp_async16(&Ws[row * GSTR + c4], Wbase + (size_t)row * K + c4);
        }
        CP_COMMIT();
    }

    for (int it = 0; it < NIT; it++) {
        const int s = it & 1;
        __syncthreads();   // all warps done computing stage 1-s (prev iter)
        if (it + 1 < NIT) {
            const int k0 = (it + 1) * GBK;
            const int so = (1 - s) * GBM * GSTR;
#pragma unroll
            for (int i = 0; i < 4; i++) {
                const int cid = tid + i * 128;
                const int row = cid >> 2;
                const int c4  = (cid & 3) * 4;
                cp_async16(&As[so + row * GSTR + c4],
                           Abase + (size_t)row * K + k0 + c4);
                cp_async16(&Ws[so + row * GSTR + c4],
                           Wbase + (size_t)row * K + k0 + c4);
            }
        }
        CP_COMMIT();
        CP_WAIT1();        // stage s data arrived (only newest group pending)
        __syncthreads();

        const unsigned sob = (unsigned)(s * GBM * GSTR) * 4u;
#pragma unroll
        for (int ks = 0; ks < 2; ks++) {
            const unsigned kb = sob + ks * 32u;   // ks*8 floats
            unsigned af[4][4];
#pragma unroll
            for (int mt = 0; mt < 4; mt++)
                LDSM4(af[mt][0], af[mt][1], af[mt][2], af[mt][3], a_ad[mt] + kb);
            unsigned bf[8][2];
#pragma unroll
            for (int p = 0; p < 4; p++)
                LDSM4(bf[2 * p][0], bf[2 * p][1], bf[2 * p + 1][0], bf[2 * p + 1][1],
                      b_ad[p] + kb);
#pragma unroll
            for (int mt = 0; mt < 4; mt++)
#pragma unroll
                for (int nt = 0; nt < 8; nt++)
                    mma_tf32(acc[mt][nt][0], acc[mt][nt][1],
                             acc[mt][nt][2], acc[mt][nt][3],
                             af[mt][0], af[mt][1], af[mt][2], af[mt][3],
                             bf[nt][0], bf[nt][1]);
        }
    }

    // epilogue: bias + float2 stores
#pragma unroll
    for (int nt = 0; nt < 8; nt++) {
        const int col = bn + wn + nt * 8 + 2 * qc;
        const float2 bv = *(const float2*)(bias + col);
#pragma unroll
        for (int mt = 0; mt < 4; mt++) {
            const int r0 = bm + wm + mt * 16 + qr;
            float2 v0 = make_float2(acc[mt][nt][0] + bv.x, acc[mt][nt][1] + bv.y);
            float2 v1 = make_float2(acc[mt][nt][2] + bv.x, acc[mt][nt][3] + bv.y);
            *(float2*)(C + (size_t)r0 * N + col)       = v0;
            *(float2*)(C + (size_t)(r0 + 8) * N + col) = v1;
        }
    }
}

// ---------------------------------------------------------------------------
// Flash attention v3: 128-query tile, 4 warps, warp tile 32x64 (mt=2, nt=8).
// ldmatrix for Q/K/P fragments (strides 68 -> 4 mod 32, conflict-free),
// scalar LDS for V (stride 72, conflict-free pattern 8qc+qr).
// Softmax scale 1/8 folded into Q at load (exact under rna: power of two).
// Output rna-rounded in epilogue so out-proj cp.async is lossless.
// ---------------------------------------------------------------------------
#define AQ   128
#define QSTR 68
#define KSTR 68
#define VSTR 72
#define PSTR 68
#define ATT_SMEM ((AQ * QSTR + 64 * KSTR + 64 * VSTR + AQ * PSTR) * 4)  // 105472

__global__ __launch_bounds__(128) void attn_tf32_v3(
    const float* __restrict__ qkv, float* __restrict__ out)
{
    extern __shared__ float smem[];
    float* Qs = smem;                        // 128*68
    float* Ks = Qs + AQ * QSTR;              // 64*68
    float* Vs = Ks + 64 * KSTR;              // 64*72
    float* Ps = Vs + 64 * VSTR;              // 128*68

    const int bh = blockIdx.y;
    const int b  = bh >> 4;
    const int h  = bh & 15;
    const int q0 = blockIdx.x * AQ;

    const int tid  = threadIdx.x;
    const int lane = tid & 31;
    const int wid  = tid >> 5;
    const int wrow = wid * 32;               // warp owns 32 query rows
    const int qr = lane >> 2;
    const int qc = lane & 3;

    const int arow = (lane & 7) + 8 * ((lane >> 3) & 1);
    const int acol = 4 * (lane >> 4);
    const int brow = (lane & 7) + 8 * (lane >> 4);
    const int bcol = 4 * ((lane >> 3) & 1);

    const unsigned Qs_u = (unsigned)__cvta_generic_to_shared(Qs);
    const unsigned Ks_u = (unsigned)__cvta_generic_to_shared(Ks);
    const unsigned Ps_u = (unsigned)__cvta_generic_to_shared(Ps);
    unsigned q_ad[2], p_ad[2], k_ad[4];
#pragma unroll
    for (int mt = 0; mt < 2; mt++) {
        q_ad[mt] = Qs_u + ((wrow + mt * 16 + arow) * QSTR + acol) * 4u;
        p_ad[mt] = Ps_u + ((wrow + mt * 16 + arow) * PSTR + acol) * 4u;
    }
#pragma unroll
    for (int p = 0; p < 4; p++)
        k_ad[p] = Ks_u + ((p * 16 + brow) * KSTR + bcol) * 4u;

    const float* base = qkv + (size_t)b * T_SZ * D3;
    const int hoff = h * DHEAD;

    // Load Q tile (128 x 64) -> tf32 smem, folding the 1/8 softmax scale
#pragma unroll
    for (int i = 0; i < 16; i++) {
        const int fidx = tid + i * 128;        // 0..2047
        const int row = fidx >> 4;
        const int d4  = fidx & 15;
        float4 v = *(const float4*)(base + (size_t)(q0 + row) * D3 + hoff + d4 * 4);
        float* dst = &Qs[row * QSTR + d4 * 4];
        dst[0] = __uint_as_float(f2tf(v.x * 0.125f));
        dst[1] = __uint_as_float(f2tf(v.y * 0.125f));
        dst[2] = __uint_as_float(f2tf(v.z * 0.125f));
        dst[3] = __uint_as_float(f2tf(v.w * 0.125f));
    }

    float mi[2][2], li[2][2];
#pragma unroll
    for (int mt = 0; mt < 2; mt++) {
        mi[mt][0] = -INFINITY; mi[mt][1] = -INFINITY;
        li[mt][0] = 0.f;       li[mt][1] = 0.f;
    }
    float oacc[2][8][4];
#pragma unroll
    for (int mt = 0; mt < 2; mt++)
#pragma unroll
        for (int nt = 0; nt < 8; nt++)
#pragma unroll
            for (int r = 0; r < 4; r++) oacc[mt][nt][r] = 0.f;

    for (int kt = 0; kt < T_SZ / 64; kt++) {
        const int k0 = kt * 64;
        __syncthreads();   // all warps done with previous Ks/Vs; Q visible
#pragma unroll
        for (int i = 0; i < 8; i++) {
            const int fidx = tid + i * 128;     // 0..1023
            const int row = fidx >> 4;
            const int d4  = fidx & 15;
            const float* rp = base + (size_t)(k0 + row) * D3 + hoff + d4 * 4;
            float4 kv = *(const float4*)(rp + D_MODEL);
            float4 vv = *(const float4*)(rp + 2 * D_MODEL);
            float* kd = &Ks[row * KSTR + d4 * 4];
            kd[0] = __uint_as_float(f2tf(kv.x));
            kd[1] = __uint_as_float(f2tf(kv.y));
            kd[2] = __uint_as_float(f2tf(kv.z));
            kd[3] = __uint_as_float(f2tf(kv.w));
            float* vd = &Vs[row * VSTR + d4 * 4];
            vd[0] = __uint_as_float(f2tf(vv.x));
            vd[1] = __uint_as_float(f2tf(vv.y));
            vd[2] = __uint_as_float(f2tf(vv.z));
            vd[3] = __uint_as_float(f2tf(vv.w));
        }
        __syncthreads();

        // ---- S = (Q/8) K^T : warp computes 32x64 (mt2 x nt8 x ks8) ----
        float sacc[2][8][4];
#pragma unroll
        for (int mt = 0; mt < 2; mt++)
#pragma unroll
            for (int nt = 0; nt < 8; nt++)
#pragma unroll
                for (int r = 0; r < 4; r++) sacc[mt][nt][r] = 0.f;

#pragma unroll
        for (int ks = 0; ks < 8; ks++) {
            const unsigned kb = ks * 32u;
            unsigned af[2][4];
#pragma unroll
            for (int mt = 0; mt < 2; mt++)
                LDSM4(af[mt][0], af[mt][1], af[mt][2], af[mt][3], q_ad[mt] + kb);
            unsigned bf[8][2];
#pragma unroll
            for (int p = 0; p < 4; p++)
                LDSM4(bf[2 * p][0], bf[2 * p][1], bf[2 * p + 1][0], bf[2 * p + 1][1],
                      k_ad[p] + kb);
#pragma unroll
            for (int nt = 0; nt < 8; nt++)
#pragma unroll
                for (int mt = 0; mt < 2; mt++)
                    mma_tf32(sacc[mt][nt][0], sacc[mt][nt][1],
                             sacc[mt][nt][2], sacc[mt][nt][3],
                             af[mt][0], af[mt][1], af[mt][2], af[mt][3],
                             bf[nt][0], bf[nt][1]);
        }

        // ---- online softmax per mt (S already scaled via Q) ----
#pragma unroll
        for (int mt = 0; mt < 2; mt++) {
            float mA = -INFINITY, mB = -INFINITY;
#pragma unroll
            for (int nt = 0; nt < 8; nt++) {
                mA = fmaxf(mA, fmaxf(sacc[mt][nt][0], sacc[mt][nt][1]));
                mB = fmaxf(mB, fmaxf(sacc[mt][nt][2], sacc[mt][nt][3]));
            }
            mA = fmaxf(mA, __shfl_xor_sync(0xffffffffu, mA, 1));
            mA = fmaxf(mA, __shfl_xor_sync(0xffffffffu, mA, 2));
            mB = fmaxf(mB, __shfl_xor_sync(0xffffffffu, mB, 1));
            mB = fmaxf(mB, __shfl_xor_sync(0xffffffffu, mB, 2));
            const float mnA = fmaxf(mi[mt][0], mA);
            const float mnB = fmaxf(mi[mt][1], mB);
            const float corrA = __expf(mi[mt][0] - mnA);
            const float corrB = __expf(mi[mt][1] - mnB);

            float psA = 0.f, psB = 0.f;
            const int prA = (wrow + mt * 16 + qr) * PSTR;
            const int prB = (wrow + mt * 16 + qr + 8) * PSTR;
#pragma unroll
            for (int nt = 0; nt < 8; nt++) {
                const int col = nt * 8 + 2 * qc;
                float p0 = __uint_as_float(f2tf(__expf(sacc[mt][nt][0] - mnA)));
                float p1 = __uint_as_float(f2tf(__expf(sacc[mt][nt][1] - mnA)));
                float p2 = __uint_as_float(f2tf(__expf(sacc[mt][nt][2] - mnB)));
                float p3 = __uint_as_float(f2tf(__expf(sacc[mt][nt][3] - mnB)));
                psA += p0 + p1;
                psB += p2 + p3;
                *(float2*)(&Ps[prA + col]) = make_float2(p0, p1);
                *(float2*)(&Ps[prB + col]) = make_float2(p2, p3);
            }
            psA += __shfl_xor_sync(0xffffffffu, psA, 1);
            psA += __shfl_xor_sync(0xffffffffu, psA, 2);
            psB += __shfl_xor_sync(0xffffffffu, psB, 1);
            psB += __shfl_xor_sync(0xffffffffu, psB, 2);
            li[mt][0] = li[mt][0] * corrA + psA;
            li[mt][1] = li[mt][1] * corrB + psB;
            mi[mt][0] = mnA; mi[mt][1] = mnB;

#pragma unroll
            for (int nt = 0; nt < 8; nt++) {
                oacc[mt][nt][0] *= corrA; oacc[mt][nt][1] *= corrA;
                oacc[mt][nt][2] *= corrB; oacc[mt][nt][3] *= corrB;
            }
        }
        __syncwarp();   // this warp's Ps rows written before A-frag reads

        // ---- O += P V ----
#pragma unroll
        for (int ks = 0; ks < 8; ks++) {
            const unsigned kb = ks * 32u;
            unsigned af[2][4];
#pragma unroll
            for (int mt = 0; mt < 2; mt++)
                LDSM4(af[mt][0], af[mt][1], af[mt][2], af[mt][3], p_ad[mt] + kb);
#pragma unroll
            for (int nt = 0; nt < 8; nt++) {
                const unsigned b0 = __float_as_uint(Vs[(ks * 8 + qc) * VSTR + nt * 8 + qr]);
                const unsigned b1 = __float_as_uint(Vs[(ks * 8 + qc + 4) * VSTR + nt * 8 + qr]);
#pragma unroll
                for (int mt = 0; mt < 2; mt++)
                    mma_tf32(oacc[mt][nt][0], oacc[mt][nt][1],
                             oacc[mt][nt][2], oacc[mt][nt][3],
                             af[mt][0], af[mt][1], af[mt][2], af[mt][3],
                             b0, b1);
            }
        }
    }

    // epilogue: rna-round so the out-proj GEMM's cp.async copy is lossless tf32
#pragma unroll
    for (int mt = 0; mt < 2; mt++) {
        const float invA = 1.f / li[mt][0];
        const float invB = 1.f / li[mt][1];
        const int rowA = q0 + wrow + mt * 16 + qr;
        float* opA = out + (size_t)(b * T_SZ + rowA) * D_MODEL + hoff;
        float* opB = opA + (size_t)8 * D_MODEL;
#pragma unroll
        for (int nt = 0; nt < 8; nt++) {
            const int col = nt * 8 + 2 * qc;
            *(float2*)(opA + col) = make_float2(
                __uint_as_float(f2tf(oacc[mt][nt][0] * invA)),
                __uint_as_float(f2tf(oacc[mt][nt][1] * invA)));
            *(float2*)(opB + col) = make_float2(
                __uint_as_float(f2tf(oacc[mt][nt][2] * invB)),
                __uint_as_float(f2tf(oacc[mt][nt][3] * invB)));
        }
    }
}

// ---------------------------------------------------------------------------
// Launch
// ---------------------------------------------------------------------------
extern "C" void kernel_launch(void* const* d_in, const int* in_sizes, int n_in,
                              void* d_out, int out_size)
{
    const float* x     = (const float*)d_in[0];
    const float* qkv_w = (const float*)d_in[1];
    const float* qkv_b = (const float*)d_in[2];
    const float* out_w = (const float*)d_in[3];
    const float* out_b = (const float*)d_in[4];
    float* out = (float*)d_out;

    float *qkvbuf, *attbuf, *xc, *wq, *wo;
    cudaGetSymbolAddress((void**)&qkvbuf, g_qkv);
    cudaGetSymbolAddress((void**)&attbuf, g_att);
    cudaGetSymbolAddress((void**)&xc, g_xc);
    cudaGetSymbolAddress((void**)&wq, g_wq);
    cudaGetSymbolAddress((void**)&wo, g_wo);

    cudaFuncSetAttribute(gemm_tf32_v3, cudaFuncAttributeMaxDynamicSharedMemorySize,
                         GEMM_SMEM);
    cudaFuncSetAttribute(attn_tf32_v3, cudaFuncAttributeMaxDynamicSharedMemorySize,
                         ATT_SMEM);

    // 0) pre-round GEMM inputs to tf32-rna (makes cp.async truncation lossless)
    {
        const int n1 = MROWS * D_MODEL / 4;
        const int n2 = D3 * D_MODEL / 4;
        const int n3 = D_MODEL * D_MODEL / 4;
        cvt_tf32_rna<<<(n1 + 255) / 256, 256>>>(x, xc, n1);
        cvt_tf32_rna<<<(n2 + 255) / 256, 256>>>(qkv_w, wq, n2);
        cvt_tf32_rna<<<(n3 + 255) / 256, 256>>>(out_w, wo, n3);
    }

    // 1) QKV projection: [8192,1024] @ [3072,1024]^T + b -> [8192,3072]
    gemm_tf32_v3<<<dim3(D3 / GBN, MROWS / GBM), 128, GEMM_SMEM>>>(
        xc, wq, qkv_b, qkvbuf, MROWS, D3, D_MODEL);

    // 2) Attention: 64 (b,h) pairs x 16 query tiles of 128
    attn_tf32_v3<<<dim3(T_SZ / AQ, B_SZ * NHEAD), 128, ATT_SMEM>>>(qkvbuf, attbuf);

    // 3) Output projection: [8192,1024] @ [1024,1024]^T + b -> [8192,1024]
    gemm_tf32_v3<<<dim3(D_MODEL / GBN, MROWS / GBM), 128, GEMM_SMEM>>>(
        attbuf, out_w /*unused path kept for clarity*/ == out_w ? wo : wo, out_b, out,
        MROWS, D_MODEL, D_MODEL);
}

// round 10
// speedup vs baseline: 9.8764x; 1.2268x over previous
#include <cuda_runtime.h>
#include <cuda_fp16.h>
#include <math.h>
#include <stdint.h>

// Problem constants
#define B_SZ    4
#define T_SZ    2048
#define D_MODEL 1024
#define NHEAD   16
#define DHEAD   64
#define D3      (3 * D_MODEL)
#define MROWS   (B_SZ * T_SZ)          // 8192

// Scratch (static device globals — allocation-free per harness rules)
__device__ __half g_qkvh[(size_t)MROWS * D3];       // fp16 qkv
__device__ __half g_atth[(size_t)MROWS * D_MODEL];  // fp16 attention out
__device__ __half g_xh[(size_t)MROWS * D_MODEL];    // fp16 x
__device__ __half g_wqh[(size_t)D3 * D_MODEL];      // fp16 qkv_w
__device__ __half g_woh[(size_t)D_MODEL * D_MODEL]; // fp16 out_w

// ---------------------------------------------------------------------------
// Helpers
// ---------------------------------------------------------------------------
__device__ __forceinline__ void mma_f16(
    float& d0, float& d1, float& d2, float& d3,
    unsigned a0, unsigned a1, unsigned a2, unsigned a3,
    unsigned b0, unsigned b1)
{
    asm("mma.sync.aligned.m16n8k16.row.col.f32.f16.f16.f32 "
        "{%0,%1,%2,%3}, {%4,%5,%6,%7}, {%8,%9}, {%0,%1,%2,%3};"
        : "+f"(d0), "+f"(d1), "+f"(d2), "+f"(d3)
        : "r"(a0), "r"(a1), "r"(a2), "r"(a3), "r"(b0), "r"(b1));
}

#define LDSM4(r0, r1, r2, r3, addr) \
    asm volatile("ldmatrix.sync.aligned.m8n8.x4.shared.b16 {%0,%1,%2,%3}, [%4];" \
                 : "=r"(r0), "=r"(r1), "=r"(r2), "=r"(r3) : "r"(addr))
#define LDSM4T(r0, r1, r2, r3, addr) \
    asm volatile("ldmatrix.sync.aligned.m8n8.x4.trans.shared.b16 {%0,%1,%2,%3}, [%4];" \
                 : "=r"(r0), "=r"(r1), "=r"(r2), "=r"(r3) : "r"(addr))

__device__ __forceinline__ void cp_async16(void* smem_dst, const void* gsrc) {
    unsigned saddr = (unsigned)__cvta_generic_to_shared(smem_dst);
    asm volatile("cp.async.ca.shared.global [%0], [%1], 16;"
                 :: "r"(saddr), "l"(gsrc));
}
#define CP_COMMIT()  asm volatile("cp.async.commit_group;")
#define CP_WAIT1()   asm volatile("cp.async.wait_group 1;")
#define CP_WAIT0()   asm volatile("cp.async.wait_group 0;")

// ---------------------------------------------------------------------------
// Pre-pass: fp32 -> fp16 (rn)
// ---------------------------------------------------------------------------
__global__ __launch_bounds__(256) void cvt_f32_f16(
    const float* __restrict__ in, __half* __restrict__ out, int n4)
{
    int i = blockIdx.x * blockDim.x + threadIdx.x;
    if (i < n4) {
        float4 v = ((const float4*)in)[i];
        __half2 h0 = __floats2half2_rn(v.x, v.y);
        __half2 h1 = __floats2half2_rn(v.z, v.w);
        ((__half2*)out)[2 * i]     = h0;
        ((__half2*)out)[2 * i + 1] = h1;
    }
}

// ---------------------------------------------------------------------------
// FP16 GEMM: C[M,N] = A[M,K] @ W[N,K]^T + bias[N]   (fp32 accumulate)
// 128x128 CTA, 4 warps (2x2), warp tile 64x64, mma m16n8k16, K-chunk 32.
// Smem stride 40 halves (80B): 16B-aligned rows; ldmatrix 8-row phases hit
// banks 20r mod 32 = {0,20,8,28,16,4,24,12} -> conflict-free.
// cp.async 2-stage double buffer (R8-proven flow).
// ---------------------------------------------------------------------------
#define HBK 32
#define HSTR 40

template <bool OUT_HALF>
__global__ __launch_bounds__(128) void gemm_h(
    const __half* __restrict__ A, const __half* __restrict__ W,
    const float* __restrict__ bias, void* __restrict__ Cv,
    int M, int N, int K)
{
    __shared__ __half Ash[2][128][HSTR];
    __shared__ __half Wsh[2][128][HSTR];

    const int tid  = threadIdx.x;
    const int lane = tid & 31;
    const int wid  = tid >> 5;
    const int wm = (wid >> 1) * 64;
    const int wn = (wid & 1) * 64;
    const int bm = blockIdx.y * 128;
    const int bn = blockIdx.x * 128;
    const int qr = lane >> 2;
    const int qc = lane & 3;

    // ldmatrix lane address components
    const int arow = lane & 15;                      // A: rows 0..15
    const int acol = (lane >> 4) * 8;                // A: k chunk 0 / +8 halves
    const int brow = (lane & 7) + 8 * (lane >> 4);   // B: n within pair-of-8 rows
    const int bsel = ((lane >> 3) & 1) * 8;          // B: k chunk 0 / +8 halves

    const unsigned As_u = (unsigned)__cvta_generic_to_shared(&Ash[0][0][0]);
    const unsigned Ws_u = (unsigned)__cvta_generic_to_shared(&Wsh[0][0][0]);
    const unsigned stg = 128 * HSTR * 2;             // stage stride bytes

    unsigned a_ad[4], b_ad[4];
#pragma unroll
    for (int mt = 0; mt < 4; mt++)
        a_ad[mt] = As_u + ((wm + mt * 16 + arow) * HSTR + acol) * 2u;
#pragma unroll
    for (int p = 0; p < 4; p++)
        b_ad[p] = Ws_u + ((wn + p * 16 + brow) * HSTR + bsel) * 2u;

    const __half* Abase = A + (size_t)bm * K;
    const __half* Wbase = W + (size_t)bn * K;

    float acc[4][8][4];
#pragma unroll
    for (int mt = 0; mt < 4; mt++)
#pragma unroll
        for (int nt = 0; nt < 8; nt++)
#pragma unroll
            for (int r = 0; r < 4; r++) acc[mt][nt][r] = 0.f;

    const int NIT = K / HBK;   // 32

    // preload stage 0
#pragma unroll
    for (int i = 0; i < 4; i++) {
        const int idx = tid + i * 128;           // 0..511
        const int row = idx >> 2, c16 = idx & 3;
        cp_async16(&Ash[0][row][c16 * 8], Abase + (size_t)row * K + c16 * 8);
        cp_async16(&Wsh[0][row][c16 * 8], Wbase + (size_t)row * K + c16 * 8);
    }
    CP_COMMIT();

    for (int it = 0; it < NIT; it++) {
        const int s = it & 1;
        __syncthreads();
        if (it + 1 < NIT) {
            const int k0 = (it + 1) * HBK;
            const int ns = 1 - s;
#pragma unroll
            for (int i = 0; i < 4; i++) {
                const int idx = tid + i * 128;
                const int row = idx >> 2, c16 = idx & 3;
                cp_async16(&Ash[ns][row][c16 * 8],
                           Abase + (size_t)row * K + k0 + c16 * 8);
                cp_async16(&Wsh[ns][row][c16 * 8],
                           Wbase + (size_t)row * K + k0 + c16 * 8);
            }
        }
        CP_COMMIT();
        CP_WAIT1();
        __syncthreads();

        const unsigned so = s * stg;
#pragma unroll
        for (int ks = 0; ks < 2; ks++) {          // 2 x K=16 per chunk
            const unsigned kb = so + ks * 32u;    // 16 halves = 32B
            unsigned af[4][4];
#pragma unroll
            for (int mt = 0; mt < 4; mt++)
                LDSM4(af[mt][0], af[mt][1], af[mt][2], af[mt][3], a_ad[mt] + kb);
            unsigned bf[8][2];
#pragma unroll
            for (int p = 0; p < 4; p++)
                LDSM4(bf[2 * p][0], bf[2 * p][1], bf[2 * p + 1][0], bf[2 * p + 1][1],
                      b_ad[p] + kb);
#pragma unroll
            for (int mt = 0; mt < 4; mt++)
#pragma unroll
                for (int nt = 0; nt < 8; nt++)
                    mma_f16(acc[mt][nt][0], acc[mt][nt][1],
                            acc[mt][nt][2], acc[mt][nt][3],
                            af[mt][0], af[mt][1], af[mt][2], af[mt][3],
                            bf[nt][0], bf[nt][1]);
        }
    }

    // epilogue
#pragma unroll
    for (int nt = 0; nt < 8; nt++) {
        const int col = bn + wn + nt * 8 + 2 * qc;
        const float2 bv = *(const float2*)(bias + col);
#pragma unroll
        for (int mt = 0; mt < 4; mt++) {
            const int r0 = bm + wm + mt * 16 + qr;
            if (OUT_HALF) {
                __half* C = (__half*)Cv;
                *(__half2*)(C + (size_t)r0 * N + col) =
                    __floats2half2_rn(acc[mt][nt][0] + bv.x, acc[mt][nt][1] + bv.y);
                *(__half2*)(C + (size_t)(r0 + 8) * N + col) =
                    __floats2half2_rn(acc[mt][nt][2] + bv.x, acc[mt][nt][3] + bv.y);
            } else {
                float* C = (float*)Cv;
                *(float2*)(C + (size_t)r0 * N + col) =
                    make_float2(acc[mt][nt][0] + bv.x, acc[mt][nt][1] + bv.y);
                *(float2*)(C + (size_t)(r0 + 8) * N + col) =
                    make_float2(acc[mt][nt][2] + bv.x, acc[mt][nt][3] + bv.y);
            }
        }
    }
}

// ---------------------------------------------------------------------------
// FP16 flash attention: 128-query tile, 4 warps, warp tile 32x64,
// mma m16n8k16. K/V tiles raw-copied from fp16 qkv via cp.async.
// Strides 72 halves (144B): banks 4r mod 32 distinct per 8-row phase.
// V consumed via ldmatrix.trans (B-fragment from [key][dh] storage).
// ---------------------------------------------------------------------------
#define AQ   128
#define ASTR 72
#define ATT_SMEM ((AQ + 64 + 64 + AQ) * ASTR * 2)   // 55296 bytes

__global__ __launch_bounds__(128) void attn_h(
    const __half* __restrict__ qkv, __half* __restrict__ out)
{
    extern __shared__ __half smh[];
    __half* Qs = smh;                    // 128 x 72
    __half* Ks = Qs + AQ * ASTR;         // 64 x 72
    __half* Vs = Ks + 64 * ASTR;         // 64 x 72  ([key][dh])
    __half* Ps = Vs + 64 * ASTR;         // 128 x 72

    const int bh = blockIdx.y;
    const int b  = bh >> 4;
    const int h  = bh & 15;
    const int q0 = blockIdx.x * AQ;

    const int tid  = threadIdx.x;
    const int lane = tid & 31;
    const int wid  = tid >> 5;
    const int wrow = wid * 32;
    const int qr = lane >> 2;
    const int qc = lane & 3;

    const int arow = lane & 15;
    const int acol = (lane >> 4) * 8;
    const int brow = (lane & 7) + 8 * (lane >> 4);
    const int bsel = ((lane >> 3) & 1) * 8;
    // V trans: row = key within kstep, col = dh halves
    const int vrow = (lane & 7) + 8 * ((lane >> 3) & 1);
    const int vsel = (lane >> 4) * 8;

    const unsigned Qs_u = (unsigned)__cvta_generic_to_shared(Qs);
    const unsigned Ks_u = (unsigned)__cvta_generic_to_shared(Ks);
    const unsigned Vs_u = (unsigned)__cvta_generic_to_shared(Vs);
    const unsigned Ps_u = (unsigned)__cvta_generic_to_shared(Ps);

    unsigned q_ad[2], p_ad[2], k_ad[4], v_ad[4];
#pragma unroll
    for (int mt = 0; mt < 2; mt++) {
        q_ad[mt] = Qs_u + ((wrow + mt * 16 + arow) * ASTR + acol) * 2u;
        p_ad[mt] = Ps_u + ((wrow + mt * 16 + arow) * ASTR + acol) * 2u;
    }
#pragma unroll
    for (int p = 0; p < 4; p++) {
        k_ad[p] = Ks_u + ((p * 16 + brow) * ASTR + bsel) * 2u;
        v_ad[p] = Vs_u + (vrow * ASTR + p * 16 + vsel) * 2u;  // nt pair 2p,2p+1
    }

    const __half* base = qkv + (size_t)b * T_SZ * D3;
    const int hoff = h * DHEAD;

    // Load Q (128x64 halves), scale by 1/8 (exponent-only, exact)
    const __half2 qscale = __float2half2_rn(0.125f);
#pragma unroll
    for (int i = 0; i < 8; i++) {
        const int fidx = tid + i * 128;      // 0..1023
        const int row = fidx >> 3;
        const int c8  = fidx & 7;
        const __half2* src = (const __half2*)(base + (size_t)(q0 + row) * D3 + hoff + c8 * 8);
        __half2* dst = (__half2*)(Qs + row * ASTR + c8 * 8);
        dst[0] = __hmul2(src[0], qscale);
        dst[1] = __hmul2(src[1], qscale);
        dst[2] = __hmul2(src[2], qscale);
        dst[3] = __hmul2(src[3], qscale);
    }

    float mi[2][2], li[2][2];
#pragma unroll
    for (int mt = 0; mt < 2; mt++) {
        mi[mt][0] = -INFINITY; mi[mt][1] = -INFINITY;
        li[mt][0] = 0.f;       li[mt][1] = 0.f;
    }
    float oacc[2][8][4];
#pragma unroll
    for (int mt = 0; mt < 2; mt++)
#pragma unroll
        for (int nt = 0; nt < 8; nt++)
#pragma unroll
            for (int r = 0; r < 4; r++) oacc[mt][nt][r] = 0.f;

    for (int kt = 0; kt < T_SZ / 64; kt++) {
        const int k0 = kt * 64;
        __syncthreads();   // previous tile's consumers done; Q visible (kt=0)
        // K/V tiles: raw fp16 copies via cp.async
#pragma unroll
        for (int i = 0; i < 4; i++) {
            const int idx = tid + i * 128;   // 0..511
            const int row = idx >> 3;
            const int c8  = idx & 7;
            const __half* rp = base + (size_t)(k0 + row) * D3 + hoff + c8 * 8;
            cp_async16(Ks + row * ASTR + c8 * 8, rp + D_MODEL);
            cp_async16(Vs + row * ASTR + c8 * 8, rp + 2 * D_MODEL);
        }
        CP_COMMIT();
        CP_WAIT0();
        __syncthreads();

        // ---- S = (Q/8) K^T : 4 ksteps (k16) x 2mt x 8nt ----
        float sacc[2][8][4];
#pragma unroll
        for (int mt = 0; mt < 2; mt++)
#pragma unroll
            for (int nt = 0; nt < 8; nt++)
#pragma unroll
                for (int r = 0; r < 4; r++) sacc[mt][nt][r] = 0.f;

#pragma unroll
        for (int ks = 0; ks < 4; ks++) {
            const unsigned kb = ks * 32u;      // 16 halves
            unsigned af[2][4];
#pragma unroll
            for (int mt = 0; mt < 2; mt++)
                LDSM4(af[mt][0], af[mt][1], af[mt][2], af[mt][3], q_ad[mt] + kb);
            unsigned bf[8][2];
#pragma unroll
            for (int p = 0; p < 4; p++)
                LDSM4(bf[2 * p][0], bf[2 * p][1], bf[2 * p + 1][0], bf[2 * p + 1][1],
                      k_ad[p] + kb);
#pragma unroll
            for (int nt = 0; nt < 8; nt++)
#pragma unroll
                for (int mt = 0; mt < 2; mt++)
                    mma_f16(sacc[mt][nt][0], sacc[mt][nt][1],
                            sacc[mt][nt][2], sacc[mt][nt][3],
                            af[mt][0], af[mt][1], af[mt][2], af[mt][3],
                            bf[nt][0], bf[nt][1]);
        }

        // ---- online softmax per mt ----
#pragma unroll
        for (int mt = 0; mt < 2; mt++) {
            float mA = -INFINITY, mB = -INFINITY;
#pragma unroll
            for (int nt = 0; nt < 8; nt++) {
                mA = fmaxf(mA, fmaxf(sacc[mt][nt][0], sacc[mt][nt][1]));
                mB = fmaxf(mB, fmaxf(sacc[mt][nt][2], sacc[mt][nt][3]));
            }
            mA = fmaxf(mA, __shfl_xor_sync(0xffffffffu, mA, 1));
            mA = fmaxf(mA, __shfl_xor_sync(0xffffffffu, mA, 2));
            mB = fmaxf(mB, __shfl_xor_sync(0xffffffffu, mB, 1));
            mB = fmaxf(mB, __shfl_xor_sync(0xffffffffu, mB, 2));
            const float mnA = fmaxf(mi[mt][0], mA);
            const float mnB = fmaxf(mi[mt][1], mB);
            const float corrA = __expf(mi[mt][0] - mnA);
            const float corrB = __expf(mi[mt][1] - mnB);

            float psA = 0.f, psB = 0.f;
            __half* prA = Ps + (wrow + mt * 16 + qr) * ASTR;
            __half* prB = Ps + (wrow + mt * 16 + qr + 8) * ASTR;
#pragma unroll
            for (int nt = 0; nt < 8; nt++) {
                const int col = nt * 8 + 2 * qc;
                __half2 h01 = __floats2half2_rn(__expf(sacc[mt][nt][0] - mnA),
                                                __expf(sacc[mt][nt][1] - mnA));
                __half2 h23 = __floats2half2_rn(__expf(sacc[mt][nt][2] - mnB),
                                                __expf(sacc[mt][nt][3] - mnB));
                *(__half2*)(prA + col) = h01;
                *(__half2*)(prB + col) = h23;
                float2 f01 = __half22float2(h01);
                float2 f23 = __half22float2(h23);
                psA += f01.x + f01.y;
                psB += f23.x + f23.y;
            }
            psA += __shfl_xor_sync(0xffffffffu, psA, 1);
            psA += __shfl_xor_sync(0xffffffffu, psA, 2);
            psB += __shfl_xor_sync(0xffffffffu, psB, 1);
            psB += __shfl_xor_sync(0xffffffffu, psB, 2);
            li[mt][0] = li[mt][0] * corrA + psA;
            li[mt][1] = li[mt][1] * corrB + psB;
            mi[mt][0] = mnA; mi[mt][1] = mnB;

#pragma unroll
            for (int nt = 0; nt < 8; nt++) {
                oacc[mt][nt][0] *= corrA; oacc[mt][nt][1] *= corrA;
                oacc[mt][nt][2] *= corrB; oacc[mt][nt][3] *= corrB;
            }
        }
        __syncwarp();   // this warp's Ps rows written before A-frag reads

        // ---- O += P V : 4 ksteps (16 keys each) ----
#pragma unroll
        for (int ks = 0; ks < 4; ks++) {
            const unsigned kbA = ks * 32u;                 // P: 16 key-cols
            const unsigned kbV = ks * 16u * ASTR * 2u;     // V: 16 key-rows
            unsigned af[2][4];
#pragma unroll
            for (int mt = 0; mt < 2; mt++)
                LDSM4(af[mt][0], af[mt][1], af[mt][2], af[mt][3], p_ad[mt] + kbA);
            unsigned vf[8][2];
#pragma unroll
            for (int p = 0; p < 4; p++)
                LDSM4T(vf[2 * p][0], vf[2 * p][1], vf[2 * p + 1][0], vf[2 * p + 1][1],
                       v_ad[p] + kbV);
#pragma unroll
            for (int nt = 0; nt < 8; nt++)
#pragma unroll
                for (int mt = 0; mt < 2; mt++)
                    mma_f16(oacc[mt][nt][0], oacc[mt][nt][1],
                            oacc[mt][nt][2], oacc[mt][nt][3],
                            af[mt][0], af[mt][1], af[mt][2], af[mt][3],
                            vf[nt][0], vf[nt][1]);
        }
    }

    // epilogue -> fp16
#pragma unroll
    for (int mt = 0; mt < 2; mt++) {
        const float invA = 1.f / li[mt][0];
        const float invB = 1.f / li[mt][1];
        const int rowA = q0 + wrow + mt * 16 + qr;
        __half* opA = out + (size_t)(b * T_SZ + rowA) * D_MODEL + hoff;
        __half* opB = opA + (size_t)8 * D_MODEL;
#pragma unroll
        for (int nt = 0; nt < 8; nt++) {
            const int col = nt * 8 + 2 * qc;
            *(__half2*)(opA + col) =
                __floats2half2_rn(oacc[mt][nt][0] * invA, oacc[mt][nt][1] * invA);
            *(__half2*)(opB + col) =
                __floats2half2_rn(oacc[mt][nt][2] * invB, oacc[mt][nt][3] * invB);
        }
    }
}

// ---------------------------------------------------------------------------
// Launch
// ---------------------------------------------------------------------------
extern "C" void kernel_launch(void* const* d_in, const int* in_sizes, int n_in,
                              void* d_out, int out_size)
{
    const float* x     = (const float*)d_in[0];
    const float* qkv_w = (const float*)d_in[1];
    const float* qkv_b = (const float*)d_in[2];
    const float* out_w = (const float*)d_in[3];
    const float* out_b = (const float*)d_in[4];
    float* out = (float*)d_out;

    __half *qkvh, *atth, *xh, *wqh, *woh;
    cudaGetSymbolAddress((void**)&qkvh, g_qkvh);
    cudaGetSymbolAddress((void**)&atth, g_atth);
    cudaGetSymbolAddress((void**)&xh, g_xh);
    cudaGetSymbolAddress((void**)&wqh, g_wqh);
    cudaGetSymbolAddress((void**)&woh, g_woh);

    cudaFuncSetAttribute(attn_h, cudaFuncAttributeMaxDynamicSharedMemorySize,
                         ATT_SMEM);

    // 0) fp32 -> fp16 pre-pass
    {
        const int n1 = MROWS * D_MODEL / 4;
        const int n2 = D3 * D_MODEL / 4;
        const int n3 = D_MODEL * D_MODEL / 4;
        cvt_f32_f16<<<(n1 + 255) / 256, 256>>>(x, xh, n1);
        cvt_f32_f16<<<(n2 + 255) / 256, 256>>>(qkv_w, wqh, n2);
        cvt_f32_f16<<<(n3 + 255) / 256, 256>>>(out_w, woh, n3);
    }

    // 1) QKV projection -> fp16 qkv
    gemm_h<true><<<dim3(D3 / 128, MROWS / 128), 128>>>(
        xh, wqh, qkv_b, qkvh, MROWS, D3, D_MODEL);

    // 2) Attention -> fp16
    attn_h<<<dim3(T_SZ / AQ, B_SZ * NHEAD), 128, ATT_SMEM>>>(qkvh, atth);

    // 3) Output projection -> fp32 out
    gemm_h<false><<<dim3(D_MODEL / 128, MROWS / 128), 128>>>(
        atth, woh, out_b, out, MROWS, D_MODEL, D_MODEL);
}

// round 11
// speedup vs baseline: 15.4011x; 1.5594x over previous
#include <cuda_runtime.h>
#include <cuda_fp16.h>
#include <math.h>
#include <stdint.h>

// Problem constants
#define B_SZ    4
#define T_SZ    2048
#define D_MODEL 1024
#define NHEAD   16
#define DHEAD   64
#define D3      (3 * D_MODEL)
#define MROWS   (B_SZ * T_SZ)          // 8192

// Scratch (static device globals — allocation-free per harness rules)
__device__ __half g_qkvh[(size_t)MROWS * D3];       // fp16 qkv
__device__ __half g_atth[(size_t)MROWS * D_MODEL];  // fp16 attention out
__device__ __half g_xh[(size_t)MROWS * D_MODEL];    // fp16 x
__device__ __half g_wqh[(size_t)D3 * D_MODEL];      // fp16 qkv_w
__device__ __half g_woh[(size_t)D_MODEL * D_MODEL]; // fp16 out_w

// ---------------------------------------------------------------------------
// Helpers
// ---------------------------------------------------------------------------
__device__ __forceinline__ void mma_f16(
    float& d0, float& d1, float& d2, float& d3,
    unsigned a0, unsigned a1, unsigned a2, unsigned a3,
    unsigned b0, unsigned b1)
{
    asm("mma.sync.aligned.m16n8k16.row.col.f32.f16.f16.f32 "
        "{%0,%1,%2,%3}, {%4,%5,%6,%7}, {%8,%9}, {%0,%1,%2,%3};"
        : "+f"(d0), "+f"(d1), "+f"(d2), "+f"(d3)
        : "r"(a0), "r"(a1), "r"(a2), "r"(a3), "r"(b0), "r"(b1));
}

#define LDSM4(r0, r1, r2, r3, addr) \
    asm volatile("ldmatrix.sync.aligned.m8n8.x4.shared.b16 {%0,%1,%2,%3}, [%4];" \
                 : "=r"(r0), "=r"(r1), "=r"(r2), "=r"(r3) : "r"(addr))
#define LDSM4T(r0, r1, r2, r3, addr) \
    asm volatile("ldmatrix.sync.aligned.m8n8.x4.trans.shared.b16 {%0,%1,%2,%3}, [%4];" \
                 : "=r"(r0), "=r"(r1), "=r"(r2), "=r"(r3) : "r"(addr))

__device__ __forceinline__ void cp_async16(void* smem_dst, const void* gsrc) {
    unsigned saddr = (unsigned)__cvta_generic_to_shared(smem_dst);
    asm volatile("cp.async.ca.shared.global [%0], [%1], 16;"
                 :: "r"(saddr), "l"(gsrc));
}
#define CP_COMMIT()  asm volatile("cp.async.commit_group;")
#define CP_WAIT1()   asm volatile("cp.async.wait_group 1;")
#define CP_WAIT0()   asm volatile("cp.async.wait_group 0;")

// ---------------------------------------------------------------------------
// Pre-pass: fp32 -> fp16 (rn)
// ---------------------------------------------------------------------------
__global__ __launch_bounds__(256) void cvt_f32_f16(
    const float* __restrict__ in, __half* __restrict__ out, int n4)
{
    int i = blockIdx.x * blockDim.x + threadIdx.x;
    if (i < n4) {
        float4 v = ((const float4*)in)[i];
        ((__half2*)out)[2 * i]     = __floats2half2_rn(v.x, v.y);
        ((__half2*)out)[2 * i + 1] = __floats2half2_rn(v.z, v.w);
    }
}

// ---------------------------------------------------------------------------
// FP16 GEMM v4: C[M,N] = A[M,K] @ W[N,K]^T + bias[N]  (fp32 accumulate)
// 128x128 CTA, 4 warps (2x2), warp tile 64x64, mma m16n8k16.
// K-chunk 64 halves (4 ks-steps per barrier pair; 16 iterations total).
// Stride 72 halves (144B rows): 16B-aligned, ldmatrix banks 4r mod 32 distinct.
// cp.async 2-stage double buffer, dynamic smem 72KB.
// ---------------------------------------------------------------------------
#define HBK 64
#define HSTR 72
#define GSTG (128 * HSTR * 2)                  // stage bytes: 18432
#define GEMM_SMEM (4 * GSTG)                   // 73728

template <bool OUT_HALF>
__global__ __launch_bounds__(128) void gemm_h(
    const __half* __restrict__ A, const __half* __restrict__ W,
    const float* __restrict__ bias, void* __restrict__ Cv,
    int M, int N, int K)
{
    extern __shared__ __half gsm[];
    __half* As = gsm;                          // [2][128][72]
    __half* Ws = gsm + 2 * 128 * HSTR;         // [2][128][72]

    const int tid  = threadIdx.x;
    const int lane = tid & 31;
    const int wid  = tid >> 5;
    const int wm = (wid >> 1) * 64;
    const int wn = (wid & 1) * 64;
    const int bm = blockIdx.y * 128;
    const int bn = blockIdx.x * 128;
    const int qr = lane >> 2;
    const int qc = lane & 3;

    const int arow = lane & 15;
    const int acol = (lane >> 4) * 8;
    const int brow = (lane & 7) + 8 * (lane >> 4);
    const int bsel = ((lane >> 3) & 1) * 8;

    const unsigned As_u = (unsigned)__cvta_generic_to_shared(As);
    const unsigned Ws_u = (unsigned)__cvta_generic_to_shared(Ws);

    unsigned a_ad[4], b_ad[4];
#pragma unroll
    for (int mt = 0; mt < 4; mt++)
        a_ad[mt] = As_u + ((wm + mt * 16 + arow) * HSTR + acol) * 2u;
#pragma unroll
    for (int p = 0; p < 4; p++)
        b_ad[p] = Ws_u + ((wn + p * 16 + brow) * HSTR + bsel) * 2u;

    const __half* Abase = A + (size_t)bm * K;
    const __half* Wbase = W + (size_t)bn * K;

    float acc[4][8][4];
#pragma unroll
    for (int mt = 0; mt < 4; mt++)
#pragma unroll
        for (int nt = 0; nt < 8; nt++)
#pragma unroll
            for (int r = 0; r < 4; r++) acc[mt][nt][r] = 0.f;

    const int NIT = K / HBK;   // 16

    // fill stage helper (inlined twice): 8 A-rows + 8 W-rows per thread
#define G_FILL(sidx, koff)                                                    \
    do {                                                                      \
        __half* Ad = As + (sidx) * 128 * HSTR;                                \
        __half* Wd = Ws + (sidx) * 128 * HSTR;                                \
        _Pragma("unroll")                                                     \
        for (int i = 0; i < 8; i++) {                                         \
            const int idx = tid + i * 128;        /* 0..1023 */               \
            const int row = idx >> 3, c16 = idx & 7;                          \
            cp_async16(Ad + row * HSTR + c16 * 8,                             \
                       Abase + (size_t)row * K + (koff) + c16 * 8);           \
            cp_async16(Wd + row * HSTR + c16 * 8,                             \
                       Wbase + (size_t)row * K + (koff) + c16 * 8);           \
        }                                                                     \
        CP_COMMIT();                                                          \
    } while (0)

    G_FILL(0, 0);

    for (int it = 0; it < NIT; it++) {
        const int s = it & 1;
        __syncthreads();                       // stage 1-s free for refill
        if (it + 1 < NIT) {
            G_FILL(1 - s, (it + 1) * HBK);
        } else {
            CP_COMMIT();                       // empty group keeps count
        }
        CP_WAIT1();                            // stage s arrived
        __syncthreads();

        const unsigned so = (unsigned)(s * GSTG);
#pragma unroll
        for (int ks = 0; ks < 4; ks++) {       // 4 x K=16
            const unsigned kb = so + ks * 32u;
            unsigned af[4][4];
#pragma unroll
            for (int mt = 0; mt < 4; mt++)
                LDSM4(af[mt][0], af[mt][1], af[mt][2], af[mt][3], a_ad[mt] + kb);
            unsigned bf[8][2];
#pragma unroll
            for (int p = 0; p < 4; p++)
                LDSM4(bf[2 * p][0], bf[2 * p][1], bf[2 * p + 1][0], bf[2 * p + 1][1],
                      b_ad[p] + kb);
#pragma unroll
            for (int mt = 0; mt < 4; mt++)
#pragma unroll
                for (int nt = 0; nt < 8; nt++)
                    mma_f16(acc[mt][nt][0], acc[mt][nt][1],
                            acc[mt][nt][2], acc[mt][nt][3],
                            af[mt][0], af[mt][1], af[mt][2], af[mt][3],
                            bf[nt][0], bf[nt][1]);
        }
    }
#undef G_FILL

    // epilogue
#pragma unroll
    for (int nt = 0; nt < 8; nt++) {
        const int col = bn + wn + nt * 8 + 2 * qc;
        const float2 bv = *(const float2*)(bias + col);
#pragma unroll
        for (int mt = 0; mt < 4; mt++) {
            const int r0 = bm + wm + mt * 16 + qr;
            if (OUT_HALF) {
                __half* C = (__half*)Cv;
                *(__half2*)(C + (size_t)r0 * N + col) =
                    __floats2half2_rn(acc[mt][nt][0] + bv.x, acc[mt][nt][1] + bv.y);
                *(__half2*)(C + (size_t)(r0 + 8) * N + col) =
                    __floats2half2_rn(acc[mt][nt][2] + bv.x, acc[mt][nt][3] + bv.y);
            } else {
                float* C = (float*)Cv;
                *(float2*)(C + (size_t)r0 * N + col) =
                    make_float2(acc[mt][nt][0] + bv.x, acc[mt][nt][1] + bv.y);
                *(float2*)(C + (size_t)(r0 + 8) * N + col) =
                    make_float2(acc[mt][nt][2] + bv.x, acc[mt][nt][3] + bv.y);
            }
        }
    }
}

// ---------------------------------------------------------------------------
// FP16 flash attention v4: 128-query tile, 4 warps, warp tile 32x64.
// K/V tiles DOUBLE-BUFFERED via cp.async: tile kt+1 loads while kt computes.
// Stride 72 halves. V via ldmatrix.trans (layout verified in R10).
// ---------------------------------------------------------------------------
#define AQ   128
#define ASTR 72
#define KVSTG (64 * ASTR * 2)                  // 9216 bytes per K or V stage
// layout: Q(128) | K0(64) | K1(64) | V0(64) | V1(64) | P(128)  rows x 72 halves
#define ATT_SMEM ((AQ + 4 * 64 + AQ) * ASTR * 2)   // 73728

__global__ __launch_bounds__(128) void attn_h(
    const __half* __restrict__ qkv, __half* __restrict__ out)
{
    extern __shared__ __half smh[];
    __half* Qs = smh;                          // 128 x 72
    __half* Ks = Qs + AQ * ASTR;               // 2 x 64 x 72
    __half* Vs = Ks + 2 * 64 * ASTR;           // 2 x 64 x 72
    __half* Ps = Vs + 2 * 64 * ASTR;           // 128 x 72

    const int bh = blockIdx.y;
    const int b  = bh >> 4;
    const int h  = bh & 15;
    const int q0 = blockIdx.x * AQ;

    const int tid  = threadIdx.x;
    const int lane = tid & 31;
    const int wid  = tid >> 5;
    const int wrow = wid * 32;
    const int qr = lane >> 2;
    const int qc = lane & 3;

    const int arow = lane & 15;
    const int acol = (lane >> 4) * 8;
    const int brow = (lane & 7) + 8 * (lane >> 4);
    const int bsel = ((lane >> 3) & 1) * 8;
    const int vrow = (lane & 7) + 8 * ((lane >> 3) & 1);
    const int vsel = (lane >> 4) * 8;

    const unsigned Qs_u = (unsigned)__cvta_generic_to_shared(Qs);
    const unsigned Ks_u = (unsigned)__cvta_generic_to_shared(Ks);
    const unsigned Vs_u = (unsigned)__cvta_generic_to_shared(Vs);
    const unsigned Ps_u = (unsigned)__cvta_generic_to_shared(Ps);

    unsigned q_ad[2], p_ad[2], k_ad[4], v_ad[4];
#pragma unroll
    for (int mt = 0; mt < 2; mt++) {
        q_ad[mt] = Qs_u + ((wrow + mt * 16 + arow) * ASTR + acol) * 2u;
        p_ad[mt] = Ps_u + ((wrow + mt * 16 + arow) * ASTR + acol) * 2u;
    }
#pragma unroll
    for (int p = 0; p < 4; p++) {
        k_ad[p] = Ks_u + ((p * 16 + brow) * ASTR + bsel) * 2u;
        v_ad[p] = Vs_u + (vrow * ASTR + p * 16 + vsel) * 2u;
    }

    const __half* base = qkv + (size_t)b * T_SZ * D3;
    const int hoff = h * DHEAD;

    // K/V stage fill: 4 K-rows + 4 V-rows of 8x16B per thread
#define A_FILL(sidx, k0)                                                      \
    do {                                                                      \
        __half* Kd = Ks + (sidx) * 64 * ASTR;                                 \
        __half* Vd = Vs + (sidx) * 64 * ASTR;                                 \
        _Pragma("unroll")                                                     \
        for (int i = 0; i < 4; i++) {                                         \
            const int idx = tid + i * 128;       /* 0..511 */                 \
            const int row = idx >> 3, c8 = idx & 7;                           \
            const __half* rp = base + (size_t)((k0) + row) * D3 + hoff + c8 * 8; \
            cp_async16(Kd + row * ASTR + c8 * 8, rp + D_MODEL);               \
            cp_async16(Vd + row * ASTR + c8 * 8, rp + 2 * D_MODEL);           \
        }                                                                     \
        CP_COMMIT();                                                          \
    } while (0)

    // Load Q (128x64 halves), scale by 1/8 (exponent-only, exact)
    const __half2 qscale = __float2half2_rn(0.125f);
#pragma unroll
    for (int i = 0; i < 8; i++) {
        const int fidx = tid + i * 128;
        const int row = fidx >> 3;
        const int c8  = fidx & 7;
        const __half2* src = (const __half2*)(base + (size_t)(q0 + row) * D3 + hoff + c8 * 8);
        __half2* dst = (__half2*)(Qs + row * ASTR + c8 * 8);
        dst[0] = __hmul2(src[0], qscale);
        dst[1] = __hmul2(src[1], qscale);
        dst[2] = __hmul2(src[2], qscale);
        dst[3] = __hmul2(src[3], qscale);
    }

    A_FILL(0, 0);                              // prefetch tile 0

    float mi[2][2], li[2][2];
#pragma unroll
    for (int mt = 0; mt < 2; mt++) {
        mi[mt][0] = -INFINITY; mi[mt][1] = -INFINITY;
        li[mt][0] = 0.f;       li[mt][1] = 0.f;
    }
    float oacc[2][8][4];
#pragma unroll
    for (int mt = 0; mt < 2; mt++)
#pragma unroll
        for (int nt = 0; nt < 8; nt++)
#pragma unroll
            for (int r = 0; r < 4; r++) oacc[mt][nt][r] = 0.f;

    const int NKT = T_SZ / 64;                 // 32... (64-key tiles)

    for (int kt = 0; kt < NKT; kt++) {
        const int s = kt & 1;
        __syncthreads();                       // stage 1-s consumers done; Q visible
        if (kt + 1 < NKT) {
            A_FILL(1 - s, (kt + 1) * 64);
        } else {
            CP_COMMIT();
        }
        CP_WAIT1();                            // stage s arrived
        __syncthreads();

        const unsigned soff = (unsigned)(s * KVSTG);

        // ---- S = (Q/8) K^T ----
        float sacc[2][8][4];
#pragma unroll
        for (int mt = 0; mt < 2; mt++)
#pragma unroll
            for (int nt = 0; nt < 8; nt++)
#pragma unroll
                for (int r = 0; r < 4; r++) sacc[mt][nt][r] = 0.f;

#pragma unroll
        for (int ks = 0; ks < 4; ks++) {
            const unsigned kb = ks * 32u;
            unsigned af[2][4];
#pragma unroll
            for (int mt = 0; mt < 2; mt++)
                LDSM4(af[mt][0], af[mt][1], af[mt][2], af[mt][3], q_ad[mt] + kb);
            unsigned bf[8][2];
#pragma unroll
            for (int p = 0; p < 4; p++)
                LDSM4(bf[2 * p][0], bf[2 * p][1], bf[2 * p + 1][0], bf[2 * p + 1][1],
                      k_ad[p] + kb + soff);
#pragma unroll
            for (int nt = 0; nt < 8; nt++)
#pragma unroll
                for (int mt = 0; mt < 2; mt++)
                    mma_f16(sacc[mt][nt][0], sacc[mt][nt][1],
                            sacc[mt][nt][2], sacc[mt][nt][3],
                            af[mt][0], af[mt][1], af[mt][2], af[mt][3],
                            bf[nt][0], bf[nt][1]);
        }

        // ---- online softmax per mt ----
#pragma unroll
        for (int mt = 0; mt < 2; mt++) {
            float mA = -INFINITY, mB = -INFINITY;
#pragma unroll
            for (int nt = 0; nt < 8; nt++) {
                mA = fmaxf(mA, fmaxf(sacc[mt][nt][0], sacc[mt][nt][1]));
                mB = fmaxf(mB, fmaxf(sacc[mt][nt][2], sacc[mt][nt][3]));
            }
            mA = fmaxf(mA, __shfl_xor_sync(0xffffffffu, mA, 1));
            mA = fmaxf(mA, __shfl_xor_sync(0xffffffffu, mA, 2));
            mB = fmaxf(mB, __shfl_xor_sync(0xffffffffu, mB, 1));
            mB = fmaxf(mB, __shfl_xor_sync(0xffffffffu, mB, 2));
            const float mnA = fmaxf(mi[mt][0], mA);
            const float mnB = fmaxf(mi[mt][1], mB);
            const float corrA = __expf(mi[mt][0] - mnA);
            const float corrB = __expf(mi[mt][1] - mnB);

            float psA = 0.f, psB = 0.f;
            __half* prA = Ps + (wrow + mt * 16 + qr) * ASTR;
            __half* prB = Ps + (wrow + mt * 16 + qr + 8) * ASTR;
#pragma unroll
            for (int nt = 0; nt < 8; nt++) {
                const int col = nt * 8 + 2 * qc;
                __half2 h01 = __floats2half2_rn(__expf(sacc[mt][nt][0] - mnA),
                                                __expf(sacc[mt][nt][1] - mnA));
                __half2 h23 = __floats2half2_rn(__expf(sacc[mt][nt][2] - mnB),
                                                __expf(sacc[mt][nt][3] - mnB));
                *(__half2*)(prA + col) = h01;
                *(__half2*)(prB + col) = h23;
                float2 f01 = __half22float2(h01);
                float2 f23 = __half22float2(h23);
                psA += f01.x + f01.y;
                psB += f23.x + f23.y;
            }
            psA += __shfl_xor_sync(0xffffffffu, psA, 1);
            psA += __shfl_xor_sync(0xffffffffu, psA, 2);
            psB += __shfl_xor_sync(0xffffffffu, psB, 1);
            psB += __shfl_xor_sync(0xffffffffu, psB, 2);
            li[mt][0] = li[mt][0] * corrA + psA;
            li[mt][1] = li[mt][1] * corrB + psB;
            mi[mt][0] = mnA; mi[mt][1] = mnB;

#pragma unroll
            for (int nt = 0; nt < 8; nt++) {
                oacc[mt][nt][0] *= corrA; oacc[mt][nt][1] *= corrA;
                oacc[mt][nt][2] *= corrB; oacc[mt][nt][3] *= corrB;
            }
        }
        __syncwarp();   // this warp's Ps rows written before A-frag reads

        // ---- O += P V ----
#pragma unroll
        for (int ks = 0; ks < 4; ks++) {
            const unsigned kbA = ks * 32u;
            const unsigned kbV = ks * 16u * ASTR * 2u + soff;
            unsigned af[2][4];
#pragma unroll
            for (int mt = 0; mt < 2; mt++)
                LDSM4(af[mt][0], af[mt][1], af[mt][2], af[mt][3], p_ad[mt] + kbA);
            unsigned vf[8][2];
#pragma unroll
            for (int p = 0; p < 4; p++)
                LDSM4T(vf[2 * p][0], vf[2 * p][1], vf[2 * p + 1][0], vf[2 * p + 1][1],
                       v_ad[p] + kbV);
#pragma unroll
            for (int nt = 0; nt < 8; nt++)
#pragma unroll
                for (int mt = 0; mt < 2; mt++)
                    mma_f16(oacc[mt][nt][0], oacc[mt][nt][1],
                            oacc[mt][nt][2], oacc[mt][nt][3],
                            af[mt][0], af[mt][1], af[mt][2], af[mt][3],
                            vf[nt][0], vf[nt][1]);
        }
    }
#undef A_FILL

    // epilogue -> fp16
#pragma unroll
    for (int mt = 0; mt < 2; mt++) {
        const float invA = 1.f / li[mt][0];
        const float invB = 1.f / li[mt][1];
        const int rowA = q0 + wrow + mt * 16 + qr;
        __half* opA = out + (size_t)(b * T_SZ + rowA) * D_MODEL + hoff;
        __half* opB = opA + (size_t)8 * D_MODEL;
#pragma unroll
        for (int nt = 0; nt < 8; nt++) {
            const int col = nt * 8 + 2 * qc;
            *(__half2*)(opA + col) =
                __floats2half2_rn(oacc[mt][nt][0] * invA, oacc[mt][nt][1] * invA);
            *(__half2*)(opB + col) =
                __floats2half2_rn(oacc[mt][nt][2] * invB, oacc[mt][nt][3] * invB);
        }
    }
}

// ---------------------------------------------------------------------------
// Launch
// ---------------------------------------------------------------------------
extern "C" void kernel_launch(void* const* d_in, const int* in_sizes, int n_in,
                              void* d_out, int out_size)
{
    const float* x     = (const float*)d_in[0];
    const float* qkv_w = (const float*)d_in[1];
    const float* qkv_b = (const float*)d_in[2];
    const float* out_w = (const float*)d_in[3];
    const float* out_b = (const float*)d_in[4];
    float* out = (float*)d_out;

    __half *qkvh, *atth, *xh, *wqh, *woh;
    cudaGetSymbolAddress((void**)&qkvh, g_qkvh);
    cudaGetSymbolAddress((void**)&atth, g_atth);
    cudaGetSymbolAddress((void**)&xh, g_xh);
    cudaGetSymbolAddress((void**)&wqh, g_wqh);
    cudaGetSymbolAddress((void**)&woh, g_woh);

    cudaFuncSetAttribute(gemm_h<true>, cudaFuncAttributeMaxDynamicSharedMemorySize,
                         GEMM_SMEM);
    cudaFuncSetAttribute(gemm_h<false>, cudaFuncAttributeMaxDynamicSharedMemorySize,
                         GEMM_SMEM);
    cudaFuncSetAttribute(attn_h, cudaFuncAttributeMaxDynamicSharedMemorySize,
                         ATT_SMEM);

    // 0) fp32 -> fp16 pre-pass
    {
        const int n1 = MROWS * D_MODEL / 4;
        const int n2 = D3 * D_MODEL / 4;
        const int n3 = D_MODEL * D_MODEL / 4;
        cvt_f32_f16<<<(n1 + 255) / 256, 256>>>(x, xh, n1);
        cvt_f32_f16<<<(n2 + 255) / 256, 256>>>(qkv_w, wqh, n2);
        cvt_f32_f16<<<(n3 + 255) / 256, 256>>>(out_w, woh, n3);
    }

    // 1) QKV projection -> fp16 qkv
    gemm_h<true><<<dim3(D3 / 128, MROWS / 128), 128, GEMM_SMEM>>>(
        xh, wqh, qkv_b, qkvh, MROWS, D3, D_MODEL);

    // 2) Attention -> fp16
    attn_h<<<dim3(T_SZ / AQ, B_SZ * NHEAD), 128, ATT_SMEM>>>(qkvh, atth);

    // 3) Output projection -> fp32 out
    gemm_h<false><<<dim3(D_MODEL / 128, MROWS / 128), 128, GEMM_SMEM>>>(
        atth, woh, out_b, out, MROWS, D_MODEL, D_MODEL);
}

// round 12
// speedup vs baseline: 16.7325x; 1.0864x over previous
#include <cuda_runtime.h>
#include <cuda_fp16.h>
#include <math.h>
#include <stdint.h>

// Problem constants
#define B_SZ    4
#define T_SZ    2048
#define D_MODEL 1024
#define NHEAD   16
#define DHEAD   64
#define D3      (3 * D_MODEL)
#define MROWS   (B_SZ * T_SZ)          // 8192

// Scratch (static device globals — allocation-free per harness rules)
__device__ __half g_qkvh[(size_t)MROWS * D3];       // fp16 qkv
__device__ __half g_atth[(size_t)MROWS * D_MODEL];  // fp16 attention out
__device__ __half g_xh[(size_t)MROWS * D_MODEL];    // fp16 x
__device__ __half g_wqh[(size_t)D3 * D_MODEL];      // fp16 qkv_w
__device__ __half g_woh[(size_t)D_MODEL * D_MODEL]; // fp16 out_w

// ---------------------------------------------------------------------------
// Helpers
// ---------------------------------------------------------------------------
__device__ __forceinline__ void mma_f16(
    float& d0, float& d1, float& d2, float& d3,
    unsigned a0, unsigned a1, unsigned a2, unsigned a3,
    unsigned b0, unsigned b1)
{
    asm("mma.sync.aligned.m16n8k16.row.col.f32.f16.f16.f32 "
        "{%0,%1,%2,%3}, {%4,%5,%6,%7}, {%8,%9}, {%0,%1,%2,%3};"
        : "+f"(d0), "+f"(d1), "+f"(d2), "+f"(d3)
        : "r"(a0), "r"(a1), "r"(a2), "r"(a3), "r"(b0), "r"(b1));
}

#define LDSM4(r0, r1, r2, r3, addr) \
    asm volatile("ldmatrix.sync.aligned.m8n8.x4.shared.b16 {%0,%1,%2,%3}, [%4];" \
                 : "=r"(r0), "=r"(r1), "=r"(r2), "=r"(r3) : "r"(addr))
#define LDSM4T(r0, r1, r2, r3, addr) \
    asm volatile("ldmatrix.sync.aligned.m8n8.x4.trans.shared.b16 {%0,%1,%2,%3}, [%4];" \
                 : "=r"(r0), "=r"(r1), "=r"(r2), "=r"(r3) : "r"(addr))

__device__ __forceinline__ void cp_async16(void* smem_dst, const void* gsrc) {
    unsigned saddr = (unsigned)__cvta_generic_to_shared(smem_dst);
    asm volatile("cp.async.ca.shared.global [%0], [%1], 16;"
                 :: "r"(saddr), "l"(gsrc));
}
#define CP_COMMIT()  asm volatile("cp.async.commit_group;")
#define CP_WAIT1()   asm volatile("cp.async.wait_group 1;")

// ---------------------------------------------------------------------------
// Pre-pass: fp32 -> fp16 (rn)
// ---------------------------------------------------------------------------
__global__ __launch_bounds__(256) void cvt_f32_f16(
    const float* __restrict__ in, __half* __restrict__ out, int n4)
{
    int i = blockIdx.x * blockDim.x + threadIdx.x;
    if (i < n4) {
        float4 v = ((const float4*)in)[i];
        ((__half2*)out)[2 * i]     = __floats2half2_rn(v.x, v.y);
        ((__half2*)out)[2 * i + 1] = __floats2half2_rn(v.z, v.w);
    }
}

// ---------------------------------------------------------------------------
// FP16 GEMM v4 (unchanged from R11): 128x128 CTA, 4 warps, warp tile 64x64,
// K-chunk 64, cp.async 2-stage, stride-72 conflict-free ldmatrix.
// ---------------------------------------------------------------------------
#define HBK 64
#define HSTR 72
#define GSTG (128 * HSTR * 2)                  // stage bytes: 18432
#define GEMM_SMEM (4 * GSTG)                   // 73728

template <bool OUT_HALF>
__global__ __launch_bounds__(128) void gemm_h(
    const __half* __restrict__ A, const __half* __restrict__ W,
    const float* __restrict__ bias, void* __restrict__ Cv,
    int M, int N, int K)
{
    extern __shared__ __half gsm[];
    __half* As = gsm;                          // [2][128][72]
    __half* Ws = gsm + 2 * 128 * HSTR;         // [2][128][72]

    const int tid  = threadIdx.x;
    const int lane = tid & 31;
    const int wid  = tid >> 5;
    const int wm = (wid >> 1) * 64;
    const int wn = (wid & 1) * 64;
    const int bm = blockIdx.y * 128;
    const int bn = blockIdx.x * 128;
    const int qr = lane >> 2;
    const int qc = lane & 3;

    const int arow = lane & 15;
    const int acol = (lane >> 4) * 8;
    const int brow = (lane & 7) + 8 * (lane >> 4);
    const int bsel = ((lane >> 3) & 1) * 8;

    const unsigned As_u = (unsigned)__cvta_generic_to_shared(As);
    const unsigned Ws_u = (unsigned)__cvta_generic_to_shared(Ws);

    unsigned a_ad[4], b_ad[4];
#pragma unroll
    for (int mt = 0; mt < 4; mt++)
        a_ad[mt] = As_u + ((wm + mt * 16 + arow) * HSTR + acol) * 2u;
#pragma unroll
    for (int p = 0; p < 4; p++)
        b_ad[p] = Ws_u + ((wn + p * 16 + brow) * HSTR + bsel) * 2u;

    const __half* Abase = A + (size_t)bm * K;
    const __half* Wbase = W + (size_t)bn * K;

    float acc[4][8][4];
#pragma unroll
    for (int mt = 0; mt < 4; mt++)
#pragma unroll
        for (int nt = 0; nt < 8; nt++)
#pragma unroll
            for (int r = 0; r < 4; r++) acc[mt][nt][r] = 0.f;

    const int NIT = K / HBK;   // 16

#define G_FILL(sidx, koff)                                                    \
    do {                                                                      \
        __half* Ad = As + (sidx) * 128 * HSTR;                                \
        __half* Wd = Ws + (sidx) * 128 * HSTR;                                \
        _Pragma("unroll")                                                     \
        for (int i = 0; i < 8; i++) {                                         \
            const int idx = tid + i * 128;                                    \
            const int row = idx >> 3, c16 = idx & 7;                          \
            cp_async16(Ad + row * HSTR + c16 * 8,                             \
                       Abase + (size_t)row * K + (koff) + c16 * 8);           \
            cp_async16(Wd + row * HSTR + c16 * 8,                             \
                       Wbase + (size_t)row * K + (koff) + c16 * 8);           \
        }                                                                     \
        CP_COMMIT();                                                          \
    } while (0)

    G_FILL(0, 0);

    for (int it = 0; it < NIT; it++) {
        const int s = it & 1;
        __syncthreads();
        if (it + 1 < NIT) {
            G_FILL(1 - s, (it + 1) * HBK);
        } else {
            CP_COMMIT();
        }
        CP_WAIT1();
        __syncthreads();

        const unsigned so = (unsigned)(s * GSTG);
#pragma unroll
        for (int ks = 0; ks < 4; ks++) {
            const unsigned kb = so + ks * 32u;
            unsigned af[4][4];
#pragma unroll
            for (int mt = 0; mt < 4; mt++)
                LDSM4(af[mt][0], af[mt][1], af[mt][2], af[mt][3], a_ad[mt] + kb);
            unsigned bf[8][2];
#pragma unroll
            for (int p = 0; p < 4; p++)
                LDSM4(bf[2 * p][0], bf[2 * p][1], bf[2 * p + 1][0], bf[2 * p + 1][1],
                      b_ad[p] + kb);
#pragma unroll
            for (int mt = 0; mt < 4; mt++)
#pragma unroll
                for (int nt = 0; nt < 8; nt++)
                    mma_f16(acc[mt][nt][0], acc[mt][nt][1],
                            acc[mt][nt][2], acc[mt][nt][3],
                            af[mt][0], af[mt][1], af[mt][2], af[mt][3],
                            bf[nt][0], bf[nt][1]);
        }
    }
#undef G_FILL

#pragma unroll
    for (int nt = 0; nt < 8; nt++) {
        const int col = bn + wn + nt * 8 + 2 * qc;
        const float2 bv = *(const float2*)(bias + col);
#pragma unroll
        for (int mt = 0; mt < 4; mt++) {
            const int r0 = bm + wm + mt * 16 + qr;
            if (OUT_HALF) {
                __half* C = (__half*)Cv;
                *(__half2*)(C + (size_t)r0 * N + col) =
                    __floats2half2_rn(acc[mt][nt][0] + bv.x, acc[mt][nt][1] + bv.y);
                *(__half2*)(C + (size_t)(r0 + 8) * N + col) =
                    __floats2half2_rn(acc[mt][nt][2] + bv.x, acc[mt][nt][3] + bv.y);
            } else {
                float* C = (float*)Cv;
                *(float2*)(C + (size_t)r0 * N + col) =
                    make_float2(acc[mt][nt][0] + bv.x, acc[mt][nt][1] + bv.y);
                *(float2*)(C + (size_t)(r0 + 8) * N + col) =
                    make_float2(acc[mt][nt][2] + bv.x, acc[mt][nt][3] + bv.y);
            }
        }
    }
}

// ---------------------------------------------------------------------------
// FP16 flash attention v5: 128-query tile, 4 warps, warp tile 32x64.
// K/V double-buffered (R11). NEW:
//  - P kept in registers: S C-frags -> half2 -> O-mma A-frags directly
//    (h01[nt] = a-reg for rows qr / local cols; h23[nt] = rows qr+8).
//  - Q A-fragments hoisted into registers once (loop-invariant).
// No P smem, no Q/P ldmatrix in the loop: 32 LDSM/tile (was 48 + 16 STS).
// ---------------------------------------------------------------------------
#define AQ   128
#define ASTR 72
#define KVSTG (64 * ASTR * 2)                  // 9216 bytes per K/V stage
// layout: Q(128) | K0(64) | K1(64) | V0(64) | V1(64)  rows x 72 halves
#define ATT_SMEM ((AQ + 4 * 64) * ASTR * 2)    // 55296

__global__ __launch_bounds__(128) void attn_h(
    const __half* __restrict__ qkv, __half* __restrict__ out)
{
    extern __shared__ __half smh[];
    __half* Qs = smh;                          // 128 x 72
    __half* Ks = Qs + AQ * ASTR;               // 2 x 64 x 72
    __half* Vs = Ks + 2 * 64 * ASTR;           // 2 x 64 x 72

    const int bh = blockIdx.y;
    const int b  = bh >> 4;
    const int h  = bh & 15;
    const int q0 = blockIdx.x * AQ;

    const int tid  = threadIdx.x;
    const int lane = tid & 31;
    const int wid  = tid >> 5;
    const int wrow = wid * 32;
    const int qr = lane >> 2;
    const int qc = lane & 3;

    const int arow = lane & 15;
    const int acol = (lane >> 4) * 8;
    const int brow = (lane & 7) + 8 * (lane >> 4);
    const int bsel = ((lane >> 3) & 1) * 8;
    const int vrow = (lane & 7) + 8 * ((lane >> 3) & 1);
    const int vsel = (lane >> 4) * 8;

    const unsigned Qs_u = (unsigned)__cvta_generic_to_shared(Qs);
    const unsigned Ks_u = (unsigned)__cvta_generic_to_shared(Ks);
    const unsigned Vs_u = (unsigned)__cvta_generic_to_shared(Vs);

    unsigned q_ad[2], k_ad[4], v_ad[4];
#pragma unroll
    for (int mt = 0; mt < 2; mt++)
        q_ad[mt] = Qs_u + ((wrow + mt * 16 + arow) * ASTR + acol) * 2u;
#pragma unroll
    for (int p = 0; p < 4; p++) {
        k_ad[p] = Ks_u + ((p * 16 + brow) * ASTR + bsel) * 2u;
        v_ad[p] = Vs_u + (vrow * ASTR + p * 16 + vsel) * 2u;
    }

    const __half* base = qkv + (size_t)b * T_SZ * D3;
    const int hoff = h * DHEAD;

#define A_FILL(sidx, k0)                                                      \
    do {                                                                      \
        __half* Kd = Ks + (sidx) * 64 * ASTR;                                 \
        __half* Vd = Vs + (sidx) * 64 * ASTR;                                 \
        _Pragma("unroll")                                                     \
        for (int i = 0; i < 4; i++) {                                         \
            const int idx = tid + i * 128;                                    \
            const int row = idx >> 3, c8 = idx & 7;                           \
            const __half* rp = base + (size_t)((k0) + row) * D3 + hoff + c8 * 8; \
            cp_async16(Kd + row * ASTR + c8 * 8, rp + D_MODEL);               \
            cp_async16(Vd + row * ASTR + c8 * 8, rp + 2 * D_MODEL);           \
        }                                                                     \
        CP_COMMIT();                                                          \
    } while (0)

    // Load Q (128x64 halves) to smem, scaled by 1/8 (exponent-only, exact)
    const __half2 qscale = __float2half2_rn(0.125f);
#pragma unroll
    for (int i = 0; i < 8; i++) {
        const int fidx = tid + i * 128;
        const int row = fidx >> 3;
        const int c8  = fidx & 7;
        const __half2* src = (const __half2*)(base + (size_t)(q0 + row) * D3 + hoff + c8 * 8);
        __half2* dst = (__half2*)(Qs + row * ASTR + c8 * 8);
        dst[0] = __hmul2(src[0], qscale);
        dst[1] = __hmul2(src[1], qscale);
        dst[2] = __hmul2(src[2], qscale);
        dst[3] = __hmul2(src[3], qscale);
    }

    A_FILL(0, 0);                              // prefetch K/V tile 0
    __syncthreads();                           // Q stores visible

    // Hoist loop-invariant Q A-fragments (4 ksteps x 2 mt)
    unsigned qf[4][2][4];
#pragma unroll
    for (int ks = 0; ks < 4; ks++)
#pragma unroll
        for (int mt = 0; mt < 2; mt++)
            LDSM4(qf[ks][mt][0], qf[ks][mt][1], qf[ks][mt][2], qf[ks][mt][3],
                  q_ad[mt] + ks * 32u);

    float mi[2][2], li[2][2];
#pragma unroll
    for (int mt = 0; mt < 2; mt++) {
        mi[mt][0] = -INFINITY; mi[mt][1] = -INFINITY;
        li[mt][0] = 0.f;       li[mt][1] = 0.f;
    }
    float oacc[2][8][4];
#pragma unroll
    for (int mt = 0; mt < 2; mt++)
#pragma unroll
        for (int nt = 0; nt < 8; nt++)
#pragma unroll
            for (int r = 0; r < 4; r++) oacc[mt][nt][r] = 0.f;

    const int NKT = T_SZ / 64;                 // 32 key tiles

    for (int kt = 0; kt < NKT; kt++) {
        const int s = kt & 1;
        __syncthreads();                       // stage 1-s consumers done
        if (kt + 1 < NKT) {
            A_FILL(1 - s, (kt + 1) * 64);
        } else {
            CP_COMMIT();
        }
        CP_WAIT1();                            // stage s arrived
        __syncthreads();

        const unsigned soff = (unsigned)(s * KVSTG);

        // ---- S = (Q/8) K^T ----
        float sacc[2][8][4];
#pragma unroll
        for (int mt = 0; mt < 2; mt++)
#pragma unroll
            for (int nt = 0; nt < 8; nt++)
#pragma unroll
                for (int r = 0; r < 4; r++) sacc[mt][nt][r] = 0.f;

#pragma unroll
        for (int ks = 0; ks < 4; ks++) {
            unsigned bf[8][2];
#pragma unroll
            for (int p = 0; p < 4; p++)
                LDSM4(bf[2 * p][0], bf[2 * p][1], bf[2 * p + 1][0], bf[2 * p + 1][1],
                      k_ad[p] + ks * 32u + soff);
#pragma unroll
            for (int nt = 0; nt < 8; nt++)
#pragma unroll
                for (int mt = 0; mt < 2; mt++)
                    mma_f16(sacc[mt][nt][0], sacc[mt][nt][1],
                            sacc[mt][nt][2], sacc[mt][nt][3],
                            qf[ks][mt][0], qf[ks][mt][1], qf[ks][mt][2], qf[ks][mt][3],
                            bf[nt][0], bf[nt][1]);
        }

        // ---- online softmax; P stays in registers as O-mma A-fragments ----
        unsigned pf01[2][8], pf23[2][8];       // h01 -> rows qr, h23 -> rows qr+8
#pragma unroll
        for (int mt = 0; mt < 2; mt++) {
            float mA = -INFINITY, mB = -INFINITY;
#pragma unroll
            for (int nt = 0; nt < 8; nt++) {
                mA = fmaxf(mA, fmaxf(sacc[mt][nt][0], sacc[mt][nt][1]));
                mB = fmaxf(mB, fmaxf(sacc[mt][nt][2], sacc[mt][nt][3]));
            }
            mA = fmaxf(mA, __shfl_xor_sync(0xffffffffu, mA, 1));
            mA = fmaxf(mA, __shfl_xor_sync(0xffffffffu, mA, 2));
            mB = fmaxf(mB, __shfl_xor_sync(0xffffffffu, mB, 1));
            mB = fmaxf(mB, __shfl_xor_sync(0xffffffffu, mB, 2));
            const float mnA = fmaxf(mi[mt][0], mA);
            const float mnB = fmaxf(mi[mt][1], mB);
            const float corrA = __expf(mi[mt][0] - mnA);
            const float corrB = __expf(mi[mt][1] - mnB);

            float psA = 0.f, psB = 0.f;
#pragma unroll
            for (int nt = 0; nt < 8; nt++) {
                __half2 h01 = __floats2half2_rn(__expf(sacc[mt][nt][0] - mnA),
                                                __expf(sacc[mt][nt][1] - mnA));
                __half2 h23 = __floats2half2_rn(__expf(sacc[mt][nt][2] - mnB),
                                                __expf(sacc[mt][nt][3] - mnB));
                pf01[mt][nt] = *(unsigned*)&h01;
                pf23[mt][nt] = *(unsigned*)&h23;
                float2 f01 = __half22float2(h01);
                float2 f23 = __half22float2(h23);
                psA += f01.x + f01.y;
                psB += f23.x + f23.y;
            }
            psA += __shfl_xor_sync(0xffffffffu, psA, 1);
            psA += __shfl_xor_sync(0xffffffffu, psA, 2);
            psB += __shfl_xor_sync(0xffffffffu, psB, 1);
            psB += __shfl_xor_sync(0xffffffffu, psB, 2);
            li[mt][0] = li[mt][0] * corrA + psA;
            li[mt][1] = li[mt][1] * corrB + psB;
            mi[mt][0] = mnA; mi[mt][1] = mnB;

#pragma unroll
            for (int nt = 0; nt < 8; nt++) {
                oacc[mt][nt][0] *= corrA; oacc[mt][nt][1] *= corrA;
                oacc[mt][nt][2] *= corrB; oacc[mt][nt][3] *= corrB;
            }
        }

        // ---- O += P V (P A-frags straight from registers) ----
#pragma unroll
        for (int ks = 0; ks < 4; ks++) {
            const unsigned kbV = ks * 16u * ASTR * 2u + soff;
            unsigned vf[8][2];
#pragma unroll
            for (int p = 0; p < 4; p++)
                LDSM4T(vf[2 * p][0], vf[2 * p][1], vf[2 * p + 1][0], vf[2 * p + 1][1],
                       v_ad[p] + kbV);
#pragma unroll
            for (int nt = 0; nt < 8; nt++)
#pragma unroll
                for (int mt = 0; mt < 2; mt++)
                    mma_f16(oacc[mt][nt][0], oacc[mt][nt][1],
                            oacc[mt][nt][2], oacc[mt][nt][3],
                            pf01[mt][2 * ks], pf23[mt][2 * ks],
                            pf01[mt][2 * ks + 1], pf23[mt][2 * ks + 1],
                            vf[nt][0], vf[nt][1]);
        }
    }
#undef A_FILL

    // epilogue -> fp16
#pragma unroll
    for (int mt = 0; mt < 2; mt++) {
        const float invA = 1.f / li[mt][0];
        const float invB = 1.f / li[mt][1];
        const int rowA = q0 + wrow + mt * 16 + qr;
        __half* opA = out + (size_t)(b * T_SZ + rowA) * D_MODEL + hoff;
        __half* opB = opA + (size_t)8 * D_MODEL;
#pragma unroll
        for (int nt = 0; nt < 8; nt++) {
            const int col = nt * 8 + 2 * qc;
            *(__half2*)(opA + col) =
                __floats2half2_rn(oacc[mt][nt][0] * invA, oacc[mt][nt][1] * invA);
            *(__half2*)(opB + col) =
                __floats2half2_rn(oacc[mt][nt][2] * invB, oacc[mt][nt][3] * invB);
        }
    }
}

// ---------------------------------------------------------------------------
// Launch
// ---------------------------------------------------------------------------
extern "C" void kernel_launch(void* const* d_in, const int* in_sizes, int n_in,
                              void* d_out, int out_size)
{
    const float* x     = (const float*)d_in[0];
    const float* qkv_w = (const float*)d_in[1];
    const float* qkv_b = (const float*)d_in[2];
    const float* out_w = (const float*)d_in[3];
    const float* out_b = (const float*)d_in[4];
    float* out = (float*)d_out;

    __half *qkvh, *atth, *xh, *wqh, *woh;
    cudaGetSymbolAddress((void**)&qkvh, g_qkvh);
    cudaGetSymbolAddress((void**)&atth, g_atth);
    cudaGetSymbolAddress((void**)&xh, g_xh);
    cudaGetSymbolAddress((void**)&wqh, g_wqh);
    cudaGetSymbolAddress((void**)&woh, g_woh);

    cudaFuncSetAttribute(gemm_h<true>, cudaFuncAttributeMaxDynamicSharedMemorySize,
                         GEMM_SMEM);
    cudaFuncSetAttribute(gemm_h<false>, cudaFuncAttributeMaxDynamicSharedMemorySize,
                         GEMM_SMEM);
    cudaFuncSetAttribute(attn_h, cudaFuncAttributeMaxDynamicSharedMemorySize,
                         ATT_SMEM);

    // 0) fp32 -> fp16 pre-pass
    {
        const int n1 = MROWS * D_MODEL / 4;
        const int n2 = D3 * D_MODEL / 4;
        const int n3 = D_MODEL * D_MODEL / 4;
        cvt_f32_f16<<<(n1 + 255) / 256, 256>>>(x, xh, n1);
        cvt_f32_f16<<<(n2 + 255) / 256, 256>>>(qkv_w, wqh, n2);
        cvt_f32_f16<<<(n3 + 255) / 256, 256>>>(out_w, woh, n3);
    }

    // 1) QKV projection -> fp16 qkv
    gemm_h<true><<<dim3(D3 / 128, MROWS / 128), 128, GEMM_SMEM>>>(
        xh, wqh, qkv_b, qkvh, MROWS, D3, D_MODEL);

    // 2) Attention -> fp16
    attn_h<<<dim3(T_SZ / AQ, B_SZ * NHEAD), 128, ATT_SMEM>>>(qkvh, atth);

    // 3) Output projection -> fp32 out
    gemm_h<false><<<dim3(D_MODEL / 128, MROWS / 128), 128, GEMM_SMEM>>>(
        atth, woh, out_b, out, MROWS, D_MODEL, D_MODEL);
}